// round 7
// baseline (speedup 1.0000x reference)
#include <cuda_runtime.h>
#include <cuda_bf16.h>
#include <math.h>

// ---------------- problem constants ----------------
#define Bb   2
#define Ls   2048
#define Dd   1024
#define Kh   32
#define Hh   32
#define Mm   4
#define Aa   4
#define TOT  2080     // 2*D + K
#define CKc  4
#define HM   128      // H*M
#define CH   128      // scan chunk length
#define NC   16       // Ls / CH

// ---------------- scratch ----------------
__device__ float g_z[(size_t)Bb * Ls * TOT];
__device__ float g_xval[(size_t)Bb * Ls * Dd];
__device__ float g_gate[(size_t)Bb * Ls * Dd];
__device__ float g_pw[(size_t)Bb * Ls * Kh];
__device__ float g_yg[(size_t)Bb * Ls * Dd];
__device__ float g_csum_re[(size_t)Bb * Kh * NC * HM];
__device__ float g_csum_im[(size_t)Bb * Kh * NC * HM];
__device__ float g_cden[(size_t)Bb * Kh * NC];
__device__ float g_WnRe[HM * Hh];
__device__ float g_WnIm[HM * Hh];
__device__ float g_w3[3];
__device__ float g_slope[Kh];

__device__ __forceinline__ unsigned f2tf(float f) {
    unsigned u;
    asm("cvt.rna.tf32.f32 %0, %1;" : "=r"(u) : "f"(f));
    return u;
}

// ---------------- prep ----------------
__global__ void prep_kernel(const float* __restrict__ dlog,
                            const float* __restrict__ ns,
                            const float* __restrict__ Wre,
                            const float* __restrict__ Wim,
                            const float* __restrict__ ds,
                            const float* __restrict__ as_)
{
    int t = threadIdx.x;
    if (t == 0) {
        float mx = fmaxf(dlog[0], fmaxf(dlog[1], dlog[2]));
        float e0 = expf(dlog[0] - mx), e1 = expf(dlog[1] - mx), e2 = expf(dlog[2] - mx);
        float inv = 1.f / (e0 + e1 + e2);
        g_w3[0] = e0 * inv; g_w3[1] = e1 * inv; g_w3[2] = e2 * inv;
    }
    if (t < Kh) {
        float xx = (t < Kh - Aa) ? ds[t] : as_[t - (Kh - Aa)];
        g_slope[t] = (xx > 20.f) ? xx : log1pf(expf(xx));
    }
    for (int i = t; i < HM * Hh; i += blockDim.x) {
        int c = i / Hh;
        g_WnRe[i] = ns[c] * Wre[i];
        g_WnIm[i] = ns[HM + c] * Wim[i];
    }
}

// ---------------- 3-stage pipelined tf32 GEMM (dynamic smem) ----------------
// C(MxN)=A(MxK)@B(KxN) row-major. BM=BN=128, BK=16, cp.async 3 stages.
// smem: As 3 x 128 x GPADK floats, then Bs 3 x 16 x GPADN floats.
#define GPADK 20
#define GPADN 132
#define GEMM_AS_FLOATS (128 * GPADK)                 // 2560
#define GEMM_BS_FLOATS (16 * GPADN)                  // 2112
#define GEMM_SMEM_BYTES ((3 * GEMM_AS_FLOATS + 3 * GEMM_BS_FLOATS) * 4)   // 56064

__global__ __launch_bounds__(256)
void tf32_gemm_pipe(const float* __restrict__ A, const float* __restrict__ B,
                    float* __restrict__ C, int Mdim, int Ndim, int Kdim)
{
    extern __shared__ __align__(16) float gsm[];
    float* AsBase = gsm;                              // 3 stages A
    float* BsBase = gsm + 3 * GEMM_AS_FLOATS;         // 3 stages B

    const int n0 = blockIdx.x * 128;
    const int m0 = blockIdx.y * 128;
    const int tid  = threadIdx.x;
    const int wid  = tid >> 5;
    const int lane = tid & 31;
    const int g  = lane >> 2;
    const int t4 = lane & 3;
    const int wm = wid & 1;
    const int wn = wid >> 1;

    float acc[4][4][4];
#pragma unroll
    for (int i = 0; i < 4; i++)
#pragma unroll
        for (int j = 0; j < 4; j++)
#pragma unroll
            for (int r = 0; r < 4; r++) acc[i][j][r] = 0.f;

    auto stage = [&](int kt, int buf) {
        int k0 = kt * 16;
        float* Asb = AsBase + buf * GEMM_AS_FLOATS;
        float* Bsb = BsBase + buf * GEMM_BS_FLOATS;
#pragma unroll
        for (int e = 0; e < 2; e++) {
            int f4 = tid * 2 + e;
            int row = f4 >> 2, c4 = f4 & 3;
            const float* src = A + (size_t)(m0 + row) * Kdim + k0 + c4 * 4;
            unsigned dst = (unsigned)__cvta_generic_to_shared(&Asb[row * GPADK + c4 * 4]);
            asm volatile("cp.async.cg.shared.global [%0], [%1], 16;\n" :: "r"(dst), "l"(src));
        }
#pragma unroll
        for (int e = 0; e < 2; e++) {
            int f4 = tid * 2 + e;
            int kk = f4 >> 5, n4 = f4 & 31;
            int ncol = n0 + n4 * 4;
            float* dstp = &Bsb[kk * GPADN + n4 * 4];
            if (ncol + 3 < Ndim) {
                const float* src = B + (size_t)(k0 + kk) * Ndim + ncol;
                unsigned dst = (unsigned)__cvta_generic_to_shared(dstp);
                asm volatile("cp.async.cg.shared.global [%0], [%1], 16;\n" :: "r"(dst), "l"(src));
            } else {
#pragma unroll
                for (int j = 0; j < 4; j++)
                    dstp[j] = (ncol + j < Ndim) ? B[(size_t)(k0 + kk) * Ndim + ncol + j] : 0.f;
            }
        }
    };

    const int KT = Kdim / 16;
    stage(0, 0);
    asm volatile("cp.async.commit_group;\n" ::: "memory");
    stage(1, 1);
    asm volatile("cp.async.commit_group;\n" ::: "memory");

    for (int kt = 0; kt < KT; kt++) {
        int buf = kt % 3;
        if (kt < KT - 1) {
            asm volatile("cp.async.wait_group 1;\n" ::: "memory");
        } else {
            asm volatile("cp.async.wait_group 0;\n" ::: "memory");
        }
        __syncthreads();
        if (kt + 2 < KT) {
            stage(kt + 2, (kt + 2) % 3);
            asm volatile("cp.async.commit_group;\n" ::: "memory");
        }

        const float* Asb = AsBase + buf * GEMM_AS_FLOATS;
        const float* Bsb = BsBase + buf * GEMM_BS_FLOATS;
#pragma unroll
        for (int kk = 0; kk < 16; kk += 8) {
            unsigned af[4][4], bf[4][2];
#pragma unroll
            for (int mi = 0; mi < 4; mi++) {
                int mb = wm * 64 + mi * 16;
                const float* p0 = &Asb[(mb + g) * GPADK + kk + t4];
                const float* p1 = &Asb[(mb + 8 + g) * GPADK + kk + t4];
                af[mi][0] = f2tf(p0[0]); af[mi][1] = f2tf(p1[0]);
                af[mi][2] = f2tf(p0[4]); af[mi][3] = f2tf(p1[4]);
            }
#pragma unroll
            for (int ni = 0; ni < 4; ni++) {
                int nb = wn * 32 + ni * 8;
                bf[ni][0] = f2tf(Bsb[(kk + t4) * GPADN + nb + g]);
                bf[ni][1] = f2tf(Bsb[(kk + t4 + 4) * GPADN + nb + g]);
            }
#pragma unroll
            for (int mi = 0; mi < 4; mi++)
#pragma unroll
                for (int ni = 0; ni < 4; ni++) {
                    asm volatile(
                        "mma.sync.aligned.m16n8k8.row.col.f32.tf32.tf32.f32 "
                        "{%0,%1,%2,%3}, {%4,%5,%6,%7}, {%8,%9}, {%0,%1,%2,%3};\n"
                        : "+f"(acc[mi][ni][0]), "+f"(acc[mi][ni][1]),
                          "+f"(acc[mi][ni][2]), "+f"(acc[mi][ni][3])
                        : "r"(af[mi][0]), "r"(af[mi][1]),
                          "r"(af[mi][2]), "r"(af[mi][3]),
                          "r"(bf[ni][0]), "r"(bf[ni][1]));
                }
        }
        __syncthreads();
    }

#pragma unroll
    for (int mi = 0; mi < 4; mi++) {
        int r0 = m0 + wm * 64 + mi * 16 + g;
#pragma unroll
        for (int ni = 0; ni < 4; ni++) {
            int c0 = n0 + wn * 32 + ni * 8 + t4 * 2;
            if (c0 + 1 < Ndim) {
                C[(size_t)r0 * Ndim + c0]           = acc[mi][ni][0];
                C[(size_t)r0 * Ndim + c0 + 1]       = acc[mi][ni][1];
                C[(size_t)(r0 + 8) * Ndim + c0]     = acc[mi][ni][2];
                C[(size_t)(r0 + 8) * Ndim + c0 + 1] = acc[mi][ni][3];
            } else if (c0 < Ndim) {
                C[(size_t)r0 * Ndim + c0]       = acc[mi][ni][0];
                C[(size_t)(r0 + 8) * Ndim + c0] = acc[mi][ni][2];
            }
        }
    }
}

// ---------------- causal depthwise conv + split ----------------
__global__ void conv_kernel(const float* __restrict__ cw, const float* __restrict__ cb,
                            const float* __restrict__ sscale)
{
    int idx = blockIdx.x * blockDim.x + threadIdx.x;
    if (idx >= Bb * Ls * TOT) return;
    int c  = idx % TOT;
    int bl = idx / TOT;
    int l  = bl % Ls;

    float acc = cb[c];
#pragma unroll
    for (int j = 0; j < CKc; j++) {
        int ll = l - j;
        if (ll >= 0)
            acc += g_z[(size_t)(bl - j) * TOT + c] * cw[(CKc - 1 - j) * TOT + c];
    }
    if (c < Dd) {
        g_xval[(size_t)bl * Dd + c] = acc;
    } else if (c < 2 * Dd) {
        float sg = 1.f / (1.f + expf(-acc));
        g_gate[(size_t)bl * Dd + (c - Dd)] = acc * sg;
    } else {
        int k = c - 2 * Dd;
        float sr = sscale[k] * acc;
        sr = fminf(20.f, fmaxf(-20.f, sr));
        float p = expf(sr);
        float dist = (k < Kh - Aa) ? (float)(Ls - 1 - l) : (float)l;
        float tw = expf(-g_slope[k] * dist);
        g_pw[(size_t)bl * Kh + k] = p * tw;
    }
}

// ---------------- pass 1: per-(b,k,chunk) partial sums (smem-staged) --------
__global__ __launch_bounds__(128)
void csum_kernel(const float* __restrict__ theta)
{
    __shared__ float XV[CH * 33];
    __shared__ float PW[CH];

    int bi    = blockIdx.x;
    int chunk = bi % NC;
    int bk    = bi / NC;
    int k     = bk % Kh;
    int b     = bk / Kh;
    int c = threadIdx.x;
    int wid = c >> 5, lane = c & 31;
    int h = c >> 2, m = c & 3;

    size_t base = ((size_t)b * Ls + chunk * CH);
    const float* xvg = &g_xval[base * Dd + k * Hh];
    for (int r = wid; r < CH; r += 4)
        XV[r * 33 + lane] = xvg[(size_t)r * Dd + lane];
    PW[c] = g_pw[(base + c) * Kh + k];
    __syncthreads();

    float th = theta[(k * Hh + h) * Mm + m];
    float w0 = g_w3[0], w1 = g_w3[1], w2 = g_w3[2];

    float are = 0.f, aim = 0.f, ad = 0.f;
    for (int i0 = 0; i0 < CH; i0 += 8) {
#pragma unroll
        for (int j = 0; j < 8; j++) {
            float xv = XV[(i0 + j) * 33 + h];
            float pwv = PW[i0 + j];
            float s, co; __sincosf(xv * th, &s, &co);
            float poly = w0 + xv * (w1 - w2 * xv);
            float t = pwv * poly;
            are += t * co; aim += t * s; ad += pwv;
        }
    }
    g_csum_re[(size_t)bi * HM + c] = are;
    g_csum_im[(size_t)bi * HM + c] = aim;
    if (c == 0) g_cden[bi] = ad;
}

// ---------------- pass 2: exclusive scan over chunks ----------------
__global__ __launch_bounds__(128)
void cscan_kernel()
{
    int bk = blockIdx.x;
    int c = threadIdx.x;
    float rr = 0.f, ri = 0.f;
    for (int ch = 0; ch < NC; ch++) {
        size_t idx = ((size_t)bk * NC + ch) * HM + c;
        float tr = g_csum_re[idx], ti = g_csum_im[idx];
        g_csum_re[idx] = rr; g_csum_im[idx] = ri;
        rr += tr; ri += ti;
    }
    if (c == 0) {
        float run = 0.f;
        for (int ch = 0; ch < NC; ch++) {
            float t = g_cden[bk * NC + ch];
            g_cden[bk * NC + ch] = run;
            run += t;
        }
    }
}

// ---------------- fused pass 3: scan + RMS scale + 3xTF32 head matvec -------
// One block per (bk, chunk). 256 threads. Dynamic smem layout (floats):
#define APAD  260                      // 256 + 4 (stride % 32 == 4 -> conflict-free)
#define OFF_A    0
#define OFF_W    (OFF_A + CH * APAD)           // 33280
#define OFF_XV   (OFF_W + 32 * APAD)           // +8320
#define OFF_PW   (OFF_XV + CH * 33)            // +4224
#define OFF_DEN  (OFF_PW + CH)
#define OFF_SC   (OFF_DEN + CH)
#define OFF_SQ4  (OFF_SC + CH)
#define FUSED_FLOATS (OFF_SQ4 + CH * 4)
#define FUSED_SMEM_BYTES (FUSED_FLOATS * 4)

__global__ __launch_bounds__(256)
void fused_scan_gemm(const float* __restrict__ theta)
{
    extern __shared__ float sm[];
    float* A   = sm + OFF_A;     // [pos][c 0..255]
    float* Ws  = sm + OFF_W;     // [hp][c 0..255]
    float* XV  = sm + OFF_XV;    // [pos][h]
    float* PW  = sm + OFF_PW;
    float* DEN = sm + OFF_DEN;
    float* SC  = sm + OFF_SC;
    float* SQ4 = sm + OFF_SQ4;   // [pos][warp]

    const int bi    = blockIdx.x;
    const int chunk = bi % NC;
    const int bk    = bi / NC;
    const int k     = bk % Kh;
    const int b     = bk / Kh;
    const int tid  = threadIdx.x;
    const int wid  = tid >> 5;
    const int lane = tid & 31;
    const int base_l = chunk * CH;

    // ---- phase 1: cooperative staging ----
    const float* xvg = &g_xval[((size_t)b * Ls + base_l) * Dd + k * Hh];
    for (int r = wid; r < CH; r += 8)
        XV[r * 33 + lane] = xvg[(size_t)r * Dd + lane];
    if (tid < CH)
        PW[tid] = g_pw[((size_t)b * Ls + base_l + tid) * Kh + k];
    for (int idx = tid; idx < 256 * 32; idx += 256) {
        int cc = idx >> 5, hp = idx & 31;
        Ws[hp * APAD + cc] = (cc < HM) ? g_WnRe[cc * Hh + hp]
                                       : g_WnIm[(cc - HM) * Hh + hp];
    }
    __syncthreads();

    // ---- phase 2: warps 0-3 scan; warp 4 den prefix ----
    if (tid < 128) {
        int c = tid;
        int h = c >> 2, m = c & 3;
        float th = theta[(k * Hh + h) * Mm + m];
        float w0 = g_w3[0], w1 = g_w3[1], w2 = g_w3[2];
        float are = g_csum_re[(size_t)bi * HM + c];
        float aim = g_csum_im[(size_t)bi * HM + c];

        for (int i0 = 0; i0 < CH; i0 += 8) {
#pragma unroll
            for (int j = 0; j < 8; j++) {
                int pos = i0 + j;
                float xv = XV[pos * 33 + h];
                float pwv = PW[pos];
                float s, co; __sincosf(xv * th, &s, &co);
                float poly = w0 + xv * (w1 - w2 * xv);
                float t = pwv * poly;
                are += t * co; aim += t * s;
                A[pos * APAD + c]       = are;
                A[pos * APAD + 128 + c] = aim;
                float sq = are * are + aim * aim;
#pragma unroll
                for (int o = 16; o > 0; o >>= 1)
                    sq += __shfl_xor_sync(0xffffffffu, sq, o);
                if (lane == 0) SQ4[pos * 4 + wid] = sq;
            }
        }
    } else if (wid == 4) {
        float den0 = g_cden[bi];
        float p0 = PW[4 * lane], p1 = PW[4 * lane + 1],
              p2 = PW[4 * lane + 2], p3 = PW[4 * lane + 3];
        float s = p0 + p1 + p2 + p3;
        float scn = s;
#pragma unroll
        for (int o = 1; o < 32; o <<= 1) {
            float t = __shfl_up_sync(0xffffffffu, scn, o);
            if (lane >= o) scn += t;
        }
        float base = den0 + scn - s;   // exclusive prefix
        DEN[4 * lane]     = base + p0;
        DEN[4 * lane + 1] = base + p0 + p1;
        DEN[4 * lane + 2] = base + p0 + p1 + p2;
        DEN[4 * lane + 3] = base + s;
    }
    __syncthreads();

    // ---- per-position scale ----
    if (tid < CH) {
        float v = SQ4[tid * 4] + SQ4[tid * 4 + 1] + SQ4[tid * 4 + 2] + SQ4[tid * 4 + 3];
        float inv_den = 1.f / fmaxf(DEN[tid], 1e-4f);
        float msq = inv_den * inv_den * v * (1.f / (2.f * HM)) + 1e-5f;
        SC[tid] = inv_den * rsqrtf(msq);
    }
    __syncthreads();

    // ---- phase 3: 8-warp 3xTF32 matvec (128 x 256) @ (256 x 32) ----
    const int g  = lane >> 2;
    const int t4 = lane & 3;
    const int mb = wid * 16;

    float acc[4][4];
#pragma unroll
    for (int i = 0; i < 4; i++)
#pragma unroll
        for (int j = 0; j < 4; j++) acc[i][j] = 0.f;

    for (int kc = 0; kc < 256; kc += 8) {
        float ar[4];
        {
            const float* p0 = &A[(mb + g) * APAD + kc + t4];
            const float* p1 = &A[(mb + 8 + g) * APAD + kc + t4];
            ar[0] = p0[0]; ar[1] = p1[0]; ar[2] = p0[4]; ar[3] = p1[4];
        }
        unsigned ahi[4], alo[4];
#pragma unroll
        for (int i = 0; i < 4; i++) {
            ahi[i] = f2tf(ar[i]);
            alo[i] = f2tf(ar[i] - __uint_as_float(ahi[i]));
        }
#pragma unroll
        for (int ni = 0; ni < 4; ni++) {
            int nb = ni * 8;
            float br0 = Ws[(nb + g) * APAD + kc + t4];
            float br1 = Ws[(nb + g) * APAD + kc + t4 + 4];
            unsigned bhi0 = f2tf(br0), bhi1 = f2tf(br1);
            unsigned blo0 = f2tf(br0 - __uint_as_float(bhi0));
            unsigned blo1 = f2tf(br1 - __uint_as_float(bhi1));
            asm volatile(
                "mma.sync.aligned.m16n8k8.row.col.f32.tf32.tf32.f32 "
                "{%0,%1,%2,%3}, {%4,%5,%6,%7}, {%8,%9}, {%0,%1,%2,%3};\n"
                : "+f"(acc[ni][0]), "+f"(acc[ni][1]), "+f"(acc[ni][2]), "+f"(acc[ni][3])
                : "r"(alo[0]), "r"(alo[1]), "r"(alo[2]), "r"(alo[3]),
                  "r"(bhi0), "r"(bhi1));
            asm volatile(
                "mma.sync.aligned.m16n8k8.row.col.f32.tf32.tf32.f32 "
                "{%0,%1,%2,%3}, {%4,%5,%6,%7}, {%8,%9}, {%0,%1,%2,%3};\n"
                : "+f"(acc[ni][0]), "+f"(acc[ni][1]), "+f"(acc[ni][2]), "+f"(acc[ni][3])
                : "r"(ahi[0]), "r"(ahi[1]), "r"(ahi[2]), "r"(ahi[3]),
                  "r"(blo0), "r"(blo1));
            asm volatile(
                "mma.sync.aligned.m16n8k8.row.col.f32.tf32.tf32.f32 "
                "{%0,%1,%2,%3}, {%4,%5,%6,%7}, {%8,%9}, {%0,%1,%2,%3};\n"
                : "+f"(acc[ni][0]), "+f"(acc[ni][1]), "+f"(acc[ni][2]), "+f"(acc[ni][3])
                : "r"(ahi[0]), "r"(ahi[1]), "r"(ahi[2]), "r"(ahi[3]),
                  "r"(bhi0), "r"(bhi1));
        }
    }

    // ---- epilogue: y = acc * scale * gate ----
    int p0 = mb + g;
    int p1 = p0 + 8;
    float sc0 = SC[p0], sc1 = SC[p1];
    size_t row0 = ((size_t)b * Ls + base_l + p0) * Dd + k * Hh;
    size_t row1 = ((size_t)b * Ls + base_l + p1) * Dd + k * Hh;
#pragma unroll
    for (int ni = 0; ni < 4; ni++) {
        int c0 = ni * 8 + t4 * 2;
        g_yg[row0 + c0]     = acc[ni][0] * sc0 * g_gate[row0 + c0];
        g_yg[row0 + c0 + 1] = acc[ni][1] * sc0 * g_gate[row0 + c0 + 1];
        g_yg[row1 + c0]     = acc[ni][2] * sc1 * g_gate[row1 + c0];
        g_yg[row1 + c0 + 1] = acc[ni][3] * sc1 * g_gate[row1 + c0 + 1];
    }
}

// ---------------- launcher ----------------
extern "C" void kernel_launch(void* const* d_in, const int* in_sizes, int n_in,
                              void* d_out, int out_size)
{
    const float* x             = (const float*)d_in[0];
    const float* in_proj_w     = (const float*)d_in[1];
    const float* conv_w        = (const float*)d_in[2];
    const float* conv_b        = (const float*)d_in[3];
    const float* theta         = (const float*)d_in[4];
    const float* decay_slopes  = (const float*)d_in[5];
    const float* anchor_slopes = (const float*)d_in[6];
    const float* score_scale   = (const float*)d_in[7];
    const float* deriv_logits  = (const float*)d_in[8];
    const float* norm_scale    = (const float*)d_in[9];
    const float* W_re          = (const float*)d_in[10];
    const float* W_im          = (const float*)d_in[11];
    const float* out_proj_w    = (const float*)d_in[12];
    float* out = (float*)d_out;

    float *z_p = nullptr, *yg_p = nullptr;
    cudaGetSymbolAddress((void**)&z_p, g_z);
    cudaGetSymbolAddress((void**)&yg_p, g_yg);

    cudaFuncSetAttribute(tf32_gemm_pipe,
                         cudaFuncAttributeMaxDynamicSharedMemorySize,
                         GEMM_SMEM_BYTES);
    cudaFuncSetAttribute(fused_scan_gemm,
                         cudaFuncAttributeMaxDynamicSharedMemorySize,
                         FUSED_SMEM_BYTES);

    prep_kernel<<<1, 256>>>(deriv_logits, norm_scale, W_re, W_im,
                            decay_slopes, anchor_slopes);

    // z = x @ in_proj_w : (4096 x 1024) @ (1024 x 2080)
    tf32_gemm_pipe<<<dim3((TOT + 127) / 128, (Bb * Ls) / 128), 256, GEMM_SMEM_BYTES>>>(
        x, in_proj_w, z_p, Bb * Ls, TOT, Dd);

    conv_kernel<<<(Bb * Ls * TOT + 255) / 256, 256>>>(conv_w, conv_b, score_scale);

    csum_kernel<<<Bb * Kh * NC, 128>>>(theta);
    cscan_kernel<<<Bb * Kh, 128>>>();
    fused_scan_gemm<<<Bb * Kh * NC, 256, FUSED_SMEM_BYTES>>>(theta);

    // out = yg @ out_proj_w : (4096 x 1024) @ (1024 x 1024)
    tf32_gemm_pipe<<<dim3(Dd / 128, (Bb * Ls) / 128), 256, GEMM_SMEM_BYTES>>>(
        yg_p, out_proj_w, out, Bb * Ls, Dd, Dd);
}

// round 10
// speedup vs baseline: 1.1477x; 1.1477x over previous
#include <cuda_runtime.h>
#include <cuda_bf16.h>
#include <math.h>

// ---------------- problem constants ----------------
#define Bb   2
#define Ls   2048
#define Dd   1024
#define Kh   32
#define Hh   32
#define Mm   4
#define Aa   4
#define TOT  2080     // 2*D + K
#define CKc  4
#define HM   128      // H*M
#define CH   128      // scan chunk length
#define NC   16       // Ls / CH

// ---------------- scratch ----------------
__device__ float g_z[(size_t)Bb * Ls * TOT];
__device__ float g_xval[(size_t)Bb * Ls * Dd];
__device__ float g_gate[(size_t)Bb * Ls * Dd];
__device__ float g_pw[(size_t)Bb * Ls * Kh];
__device__ float g_yg[(size_t)Bb * Ls * Dd];
__device__ float g_csum_re[(size_t)Bb * Kh * NC * HM];
__device__ float g_csum_im[(size_t)Bb * Kh * NC * HM];
__device__ float g_cden[(size_t)Bb * Kh * NC];
__device__ float g_WnRe[HM * Hh];
__device__ float g_WnIm[HM * Hh];
__device__ float g_w3[3];
__device__ float g_slope[Kh];

__device__ __forceinline__ unsigned f2tf(float f) {
    unsigned u;
    asm("cvt.rna.tf32.f32 %0, %1;" : "=r"(u) : "f"(f));
    return u;
}

// ---------------- prep ----------------
__global__ void prep_kernel(const float* __restrict__ dlog,
                            const float* __restrict__ ns,
                            const float* __restrict__ Wre,
                            const float* __restrict__ Wim,
                            const float* __restrict__ ds,
                            const float* __restrict__ as_)
{
    int t = threadIdx.x;
    if (t == 0) {
        float mx = fmaxf(dlog[0], fmaxf(dlog[1], dlog[2]));
        float e0 = expf(dlog[0] - mx), e1 = expf(dlog[1] - mx), e2 = expf(dlog[2] - mx);
        float inv = 1.f / (e0 + e1 + e2);
        g_w3[0] = e0 * inv; g_w3[1] = e1 * inv; g_w3[2] = e2 * inv;
    }
    if (t < Kh) {
        float xx = (t < Kh - Aa) ? ds[t] : as_[t - (Kh - Aa)];
        g_slope[t] = (xx > 20.f) ? xx : log1pf(expf(xx));
    }
    for (int i = t; i < HM * Hh; i += blockDim.x) {
        int c = i / Hh;
        g_WnRe[i] = ns[c] * Wre[i];
        g_WnIm[i] = ns[HM + c] * Wim[i];
    }
}

// ---------------- 2-stage pipelined tf32 GEMM (R4 known-good) ---------------
// C(MxN)=A(MxK)@B(KxN) row-major. BM=BN=128, BK=16, double-buffered cp.async.
#define GPADK 20
#define GPADN 132

__global__ __launch_bounds__(256, 2)
void tf32_gemm_pipe(const float* __restrict__ A, const float* __restrict__ B,
                    float* __restrict__ C, int Mdim, int Ndim, int Kdim)
{
    __shared__ __align__(16) float As[2][128 * GPADK];
    __shared__ __align__(16) float Bs[2][16 * GPADN];

    const int n0 = blockIdx.x * 128;
    const int m0 = blockIdx.y * 128;
    const int tid  = threadIdx.x;
    const int wid  = tid >> 5;
    const int lane = tid & 31;
    const int g  = lane >> 2;
    const int t4 = lane & 3;
    const int wm = wid & 1;
    const int wn = wid >> 1;

    float acc[4][4][4];
#pragma unroll
    for (int i = 0; i < 4; i++)
#pragma unroll
        for (int j = 0; j < 4; j++)
#pragma unroll
            for (int r = 0; r < 4; r++) acc[i][j][r] = 0.f;

    auto stage = [&](int kt, int buf) {
        int k0 = kt * 16;
#pragma unroll
        for (int e = 0; e < 2; e++) {
            int f4 = tid * 2 + e;
            int row = f4 >> 2, c4 = f4 & 3;
            const float* src = A + (size_t)(m0 + row) * Kdim + k0 + c4 * 4;
            unsigned dst = (unsigned)__cvta_generic_to_shared(&As[buf][row * GPADK + c4 * 4]);
            asm volatile("cp.async.cg.shared.global [%0], [%1], 16;\n" :: "r"(dst), "l"(src));
        }
#pragma unroll
        for (int e = 0; e < 2; e++) {
            int f4 = tid * 2 + e;
            int kk = f4 >> 5, n4 = f4 & 31;
            int ncol = n0 + n4 * 4;
            float* dstp = &Bs[buf][kk * GPADN + n4 * 4];
            if (ncol + 3 < Ndim) {
                const float* src = B + (size_t)(k0 + kk) * Ndim + ncol;
                unsigned dst = (unsigned)__cvta_generic_to_shared(dstp);
                asm volatile("cp.async.cg.shared.global [%0], [%1], 16;\n" :: "r"(dst), "l"(src));
            } else {
#pragma unroll
                for (int j = 0; j < 4; j++)
                    dstp[j] = (ncol + j < Ndim) ? B[(size_t)(k0 + kk) * Ndim + ncol + j] : 0.f;
            }
        }
    };

    const int KT = Kdim / 16;
    stage(0, 0);
    asm volatile("cp.async.commit_group;\n" ::: "memory");

    for (int kt = 0; kt < KT; kt++) {
        int buf = kt & 1;
        if (kt + 1 < KT) {
            stage(kt + 1, buf ^ 1);
            asm volatile("cp.async.commit_group;\n" ::: "memory");
            asm volatile("cp.async.wait_group 1;\n" ::: "memory");
        } else {
            asm volatile("cp.async.wait_group 0;\n" ::: "memory");
        }
        __syncthreads();

        const float* Asb = As[buf];
        const float* Bsb = Bs[buf];
#pragma unroll
        for (int kk = 0; kk < 16; kk += 8) {
            unsigned af[4][4], bf[4][2];
#pragma unroll
            for (int mi = 0; mi < 4; mi++) {
                int mb = wm * 64 + mi * 16;
                const float* p0 = &Asb[(mb + g) * GPADK + kk + t4];
                const float* p1 = &Asb[(mb + 8 + g) * GPADK + kk + t4];
                af[mi][0] = f2tf(p0[0]); af[mi][1] = f2tf(p1[0]);
                af[mi][2] = f2tf(p0[4]); af[mi][3] = f2tf(p1[4]);
            }
#pragma unroll
            for (int ni = 0; ni < 4; ni++) {
                int nb = wn * 32 + ni * 8;
                bf[ni][0] = f2tf(Bsb[(kk + t4) * GPADN + nb + g]);
                bf[ni][1] = f2tf(Bsb[(kk + t4 + 4) * GPADN + nb + g]);
            }
#pragma unroll
            for (int mi = 0; mi < 4; mi++)
#pragma unroll
                for (int ni = 0; ni < 4; ni++) {
                    asm volatile(
                        "mma.sync.aligned.m16n8k8.row.col.f32.tf32.tf32.f32 "
                        "{%0,%1,%2,%3}, {%4,%5,%6,%7}, {%8,%9}, {%0,%1,%2,%3};\n"
                        : "+f"(acc[mi][ni][0]), "+f"(acc[mi][ni][1]),
                          "+f"(acc[mi][ni][2]), "+f"(acc[mi][ni][3])
                        : "r"(af[mi][0]), "r"(af[mi][1]),
                          "r"(af[mi][2]), "r"(af[mi][3]),
                          "r"(bf[ni][0]), "r"(bf[ni][1]));
                }
        }
        __syncthreads();
    }

#pragma unroll
    for (int mi = 0; mi < 4; mi++) {
        int r0 = m0 + wm * 64 + mi * 16 + g;
#pragma unroll
        for (int ni = 0; ni < 4; ni++) {
            int c0 = n0 + wn * 32 + ni * 8 + t4 * 2;
            if (c0 + 1 < Ndim) {
                C[(size_t)r0 * Ndim + c0]           = acc[mi][ni][0];
                C[(size_t)r0 * Ndim + c0 + 1]       = acc[mi][ni][1];
                C[(size_t)(r0 + 8) * Ndim + c0]     = acc[mi][ni][2];
                C[(size_t)(r0 + 8) * Ndim + c0 + 1] = acc[mi][ni][3];
            } else if (c0 < Ndim) {
                C[(size_t)r0 * Ndim + c0]       = acc[mi][ni][0];
                C[(size_t)(r0 + 8) * Ndim + c0] = acc[mi][ni][2];
            }
        }
    }
}

// ---------------- causal depthwise conv + split ----------------
__global__ void conv_kernel(const float* __restrict__ cw, const float* __restrict__ cb,
                            const float* __restrict__ sscale)
{
    int idx = blockIdx.x * blockDim.x + threadIdx.x;
    if (idx >= Bb * Ls * TOT) return;
    int c  = idx % TOT;
    int bl = idx / TOT;
    int l  = bl % Ls;

    float acc = cb[c];
#pragma unroll
    for (int j = 0; j < CKc; j++) {
        int ll = l - j;
        if (ll >= 0)
            acc += g_z[(size_t)(bl - j) * TOT + c] * cw[(CKc - 1 - j) * TOT + c];
    }
    if (c < Dd) {
        g_xval[(size_t)bl * Dd + c] = acc;
    } else if (c < 2 * Dd) {
        float sg = 1.f / (1.f + expf(-acc));
        g_gate[(size_t)bl * Dd + (c - Dd)] = acc * sg;
    } else {
        int k = c - 2 * Dd;
        float sr = sscale[k] * acc;
        sr = fminf(20.f, fmaxf(-20.f, sr));
        float p = expf(sr);
        float dist = (k < Kh - Aa) ? (float)(Ls - 1 - l) : (float)l;
        float tw = expf(-g_slope[k] * dist);
        g_pw[(size_t)bl * Kh + k] = p * tw;
    }
}

// ---------------- pass 1: per-(b,k,chunk) partial sums (smem-staged) --------
__global__ __launch_bounds__(128)
void csum_kernel(const float* __restrict__ theta)
{
    __shared__ float XV[CH * 33];
    __shared__ float PW[CH];

    int bi    = blockIdx.x;
    int chunk = bi % NC;
    int bk    = bi / NC;
    int k     = bk % Kh;
    int b     = bk / Kh;
    int c = threadIdx.x;
    int wid = c >> 5, lane = c & 31;
    int h = c >> 2, m = c & 3;

    size_t base = ((size_t)b * Ls + chunk * CH);
    const float* xvg = &g_xval[base * Dd + k * Hh];
    for (int r = wid; r < CH; r += 4)
        XV[r * 33 + lane] = xvg[(size_t)r * Dd + lane];
    PW[c] = g_pw[(base + c) * Kh + k];
    __syncthreads();

    float th = theta[(k * Hh + h) * Mm + m];
    float w0 = g_w3[0], w1 = g_w3[1], w2 = g_w3[2];

    float are = 0.f, aim = 0.f, ad = 0.f;
    for (int i0 = 0; i0 < CH; i0 += 8) {
#pragma unroll
        for (int j = 0; j < 8; j++) {
            float xv = XV[(i0 + j) * 33 + h];
            float pwv = PW[i0 + j];
            float s, co; __sincosf(xv * th, &s, &co);
            float poly = w0 + xv * (w1 - w2 * xv);
            float t = pwv * poly;
            are += t * co; aim += t * s; ad += pwv;
        }
    }
    g_csum_re[(size_t)bi * HM + c] = are;
    g_csum_im[(size_t)bi * HM + c] = aim;
    if (c == 0) g_cden[bi] = ad;
}

// ---------------- pass 2: exclusive scan over chunks ----------------
__global__ __launch_bounds__(128)
void cscan_kernel()
{
    int bk = blockIdx.x;
    int c = threadIdx.x;
    float rr = 0.f, ri = 0.f;
    for (int ch = 0; ch < NC; ch++) {
        size_t idx = ((size_t)bk * NC + ch) * HM + c;
        float tr = g_csum_re[idx], ti = g_csum_im[idx];
        g_csum_re[idx] = rr; g_csum_im[idx] = ri;
        rr += tr; ri += ti;
    }
    if (c == 0) {
        float run = 0.f;
        for (int ch = 0; ch < NC; ch++) {
            float t = g_cden[bk * NC + ch];
            g_cden[bk * NC + ch] = run;
            run += t;
        }
    }
}

// ---------------- fused pass 3: scan + RMS scale + 3xTF32 head matvec -------
// One block per (bk, chunk). 256 threads. Dynamic smem layout (floats):
#define APAD  260                      // 256 + 4 (stride % 32 == 4 -> conflict-free)
#define OFF_A    0
#define OFF_W    (OFF_A + CH * APAD)           // 33280
#define OFF_XV   (OFF_W + 32 * APAD)           // +8320
#define OFF_PW   (OFF_XV + CH * 33)            // +4224
#define OFF_DEN  (OFF_PW + CH)
#define OFF_SC   (OFF_DEN + CH)
#define FUSED_FLOATS (OFF_SC + CH)
#define FUSED_SMEM_BYTES (FUSED_FLOATS * 4)

__global__ __launch_bounds__(256)
void fused_scan_gemm(const float* __restrict__ theta)
{
    extern __shared__ float sm[];
    float* A   = sm + OFF_A;     // [pos][c 0..255]
    float* Ws  = sm + OFF_W;     // [hp][c 0..255]
    float* XV  = sm + OFF_XV;    // [pos][h]
    float* PW  = sm + OFF_PW;
    float* DEN = sm + OFF_DEN;
    float* SC  = sm + OFF_SC;

    const int bi    = blockIdx.x;
    const int chunk = bi % NC;
    const int bk    = bi / NC;
    const int k     = bk % Kh;
    const int b     = bk / Kh;
    const int tid  = threadIdx.x;
    const int wid  = tid >> 5;
    const int lane = tid & 31;
    const int base_l = chunk * CH;

    // ---- phase 1: cooperative staging ----
    const float* xvg = &g_xval[((size_t)b * Ls + base_l) * Dd + k * Hh];
    for (int r = wid; r < CH; r += 8)
        XV[r * 33 + lane] = xvg[(size_t)r * Dd + lane];
    if (tid < CH)
        PW[tid] = g_pw[((size_t)b * Ls + base_l + tid) * Kh + k];
    for (int idx = tid; idx < 256 * 32; idx += 256) {
        int cc = idx >> 5, hp = idx & 31;
        Ws[hp * APAD + cc] = (cc < HM) ? g_WnRe[cc * Hh + hp]
                                       : g_WnIm[(cc - HM) * Hh + hp];
    }
    __syncthreads();

    // ---- phase 2: warps 0-3 scan (A only, no reductions); warp 4 den prefix
    if (tid < 128) {
        int c = tid;
        int h = c >> 2, m = c & 3;
        float th = theta[(k * Hh + h) * Mm + m];
        float w0 = g_w3[0], w1 = g_w3[1], w2 = g_w3[2];
        float are = g_csum_re[(size_t)bi * HM + c];
        float aim = g_csum_im[(size_t)bi * HM + c];

        for (int i0 = 0; i0 < CH; i0 += 8) {
#pragma unroll
            for (int j = 0; j < 8; j++) {
                int pos = i0 + j;
                float xv = XV[pos * 33 + h];
                float pwv = PW[pos];
                float s, co; __sincosf(xv * th, &s, &co);
                float poly = w0 + xv * (w1 - w2 * xv);
                float t = pwv * poly;
                are += t * co; aim += t * s;
                A[pos * APAD + c]       = are;
                A[pos * APAD + 128 + c] = aim;
            }
        }
    } else if (wid == 4) {
        float den0 = g_cden[bi];
        float p0 = PW[4 * lane], p1 = PW[4 * lane + 1],
              p2 = PW[4 * lane + 2], p3 = PW[4 * lane + 3];
        float s = p0 + p1 + p2 + p3;
        float scn = s;
#pragma unroll
        for (int o = 1; o < 32; o <<= 1) {
            float t = __shfl_up_sync(0xffffffffu, scn, o);
            if (lane >= o) scn += t;
        }
        float base = den0 + scn - s;   // exclusive prefix
        DEN[4 * lane]     = base + p0;
        DEN[4 * lane + 1] = base + p0 + p1;
        DEN[4 * lane + 2] = base + p0 + p1 + p2;
        DEN[4 * lane + 3] = base + s;
    }
    __syncthreads();

    // ---- phase 2b: position-parallel sum-of-squares + scale ----
    // warp w handles positions w, w+8, ..., w+120 (16 per warp).
    for (int pos = wid; pos < CH; pos += 8) {
        const float* Ap = &A[pos * APAD];
        float sq = 0.f;
#pragma unroll
        for (int j = 0; j < 8; j++) {
            float v = Ap[j * 32 + lane];
            sq += v * v;
        }
#pragma unroll
        for (int o = 16; o > 0; o >>= 1)
            sq += __shfl_xor_sync(0xffffffffu, sq, o);
        if (lane == 0) {
            float inv_den = 1.f / fmaxf(DEN[pos], 1e-4f);
            float msq = inv_den * inv_den * sq * (1.f / (2.f * HM)) + 1e-5f;
            SC[pos] = inv_den * rsqrtf(msq);
        }
    }
    __syncthreads();

    // ---- phase 3: 8-warp 3xTF32 matvec (128 x 256) @ (256 x 32) ----
    const int g  = lane >> 2;
    const int t4 = lane & 3;
    const int mb = wid * 16;

    float acc[4][4];
#pragma unroll
    for (int i = 0; i < 4; i++)
#pragma unroll
        for (int j = 0; j < 4; j++) acc[i][j] = 0.f;

    for (int kc = 0; kc < 256; kc += 8) {
        float ar[4];
        {
            const float* p0 = &A[(mb + g) * APAD + kc + t4];
            const float* p1 = &A[(mb + 8 + g) * APAD + kc + t4];
            ar[0] = p0[0]; ar[1] = p1[0]; ar[2] = p0[4]; ar[3] = p1[4];
        }
        unsigned ahi[4], alo[4];
#pragma unroll
        for (int i = 0; i < 4; i++) {
            ahi[i] = f2tf(ar[i]);
            alo[i] = f2tf(ar[i] - __uint_as_float(ahi[i]));
        }
#pragma unroll
        for (int ni = 0; ni < 4; ni++) {
            int nb = ni * 8;
            float br0 = Ws[(nb + g) * APAD + kc + t4];
            float br1 = Ws[(nb + g) * APAD + kc + t4 + 4];
            unsigned bhi0 = f2tf(br0), bhi1 = f2tf(br1);
            unsigned blo0 = f2tf(br0 - __uint_as_float(bhi0));
            unsigned blo1 = f2tf(br1 - __uint_as_float(bhi1));
            asm volatile(
                "mma.sync.aligned.m16n8k8.row.col.f32.tf32.tf32.f32 "
                "{%0,%1,%2,%3}, {%4,%5,%6,%7}, {%8,%9}, {%0,%1,%2,%3};\n"
                : "+f"(acc[ni][0]), "+f"(acc[ni][1]), "+f"(acc[ni][2]), "+f"(acc[ni][3])
                : "r"(alo[0]), "r"(alo[1]), "r"(alo[2]), "r"(alo[3]),
                  "r"(bhi0), "r"(bhi1));
            asm volatile(
                "mma.sync.aligned.m16n8k8.row.col.f32.tf32.tf32.f32 "
                "{%0,%1,%2,%3}, {%4,%5,%6,%7}, {%8,%9}, {%0,%1,%2,%3};\n"
                : "+f"(acc[ni][0]), "+f"(acc[ni][1]), "+f"(acc[ni][2]), "+f"(acc[ni][3])
                : "r"(ahi[0]), "r"(ahi[1]), "r"(ahi[2]), "r"(ahi[3]),
                  "r"(blo0), "r"(blo1));
            asm volatile(
                "mma.sync.aligned.m16n8k8.row.col.f32.tf32.tf32.f32 "
                "{%0,%1,%2,%3}, {%4,%5,%6,%7}, {%8,%9}, {%0,%1,%2,%3};\n"
                : "+f"(acc[ni][0]), "+f"(acc[ni][1]), "+f"(acc[ni][2]), "+f"(acc[ni][3])
                : "r"(ahi[0]), "r"(ahi[1]), "r"(ahi[2]), "r"(ahi[3]),
                  "r"(bhi0), "r"(bhi1));
        }
    }

    // ---- epilogue: y = acc * scale * gate ----
    int p0 = mb + g;
    int p1 = p0 + 8;
    float sc0 = SC[p0], sc1 = SC[p1];
    size_t row0 = ((size_t)b * Ls + base_l + p0) * Dd + k * Hh;
    size_t row1 = ((size_t)b * Ls + base_l + p1) * Dd + k * Hh;
#pragma unroll
    for (int ni = 0; ni < 4; ni++) {
        int c0 = ni * 8 + t4 * 2;
        g_yg[row0 + c0]     = acc[ni][0] * sc0 * g_gate[row0 + c0];
        g_yg[row0 + c0 + 1] = acc[ni][1] * sc0 * g_gate[row0 + c0 + 1];
        g_yg[row1 + c0]     = acc[ni][2] * sc1 * g_gate[row1 + c0];
        g_yg[row1 + c0 + 1] = acc[ni][3] * sc1 * g_gate[row1 + c0 + 1];
    }
}

// ---------------- launcher ----------------
extern "C" void kernel_launch(void* const* d_in, const int* in_sizes, int n_in,
                              void* d_out, int out_size)
{
    const float* x             = (const float*)d_in[0];
    const float* in_proj_w     = (const float*)d_in[1];
    const float* conv_w        = (const float*)d_in[2];
    const float* conv_b        = (const float*)d_in[3];
    const float* theta         = (const float*)d_in[4];
    const float* decay_slopes  = (const float*)d_in[5];
    const float* anchor_slopes = (const float*)d_in[6];
    const float* score_scale   = (const float*)d_in[7];
    const float* deriv_logits  = (const float*)d_in[8];
    const float* norm_scale    = (const float*)d_in[9];
    const float* W_re          = (const float*)d_in[10];
    const float* W_im          = (const float*)d_in[11];
    const float* out_proj_w    = (const float*)d_in[12];
    float* out = (float*)d_out;

    float *z_p = nullptr, *yg_p = nullptr;
    cudaGetSymbolAddress((void**)&z_p, g_z);
    cudaGetSymbolAddress((void**)&yg_p, g_yg);

    cudaFuncSetAttribute(fused_scan_gemm,
                         cudaFuncAttributeMaxDynamicSharedMemorySize,
                         FUSED_SMEM_BYTES);

    prep_kernel<<<1, 256>>>(deriv_logits, norm_scale, W_re, W_im,
                            decay_slopes, anchor_slopes);

    // z = x @ in_proj_w : (4096 x 1024) @ (1024 x 2080)
    tf32_gemm_pipe<<<dim3((TOT + 127) / 128, (Bb * Ls) / 128), 256>>>(
        x, in_proj_w, z_p, Bb * Ls, TOT, Dd);

    conv_kernel<<<(Bb * Ls * TOT + 255) / 256, 256>>>(conv_w, conv_b, score_scale);

    csum_kernel<<<Bb * Kh * NC, 128>>>(theta);
    cscan_kernel<<<Bb * Kh, 128>>>();
    fused_scan_gemm<<<Bb * Kh * NC, 256, FUSED_SMEM_BYTES>>>(theta);

    // out = yg @ out_proj_w : (4096 x 1024) @ (1024 x 1024)
    tf32_gemm_pipe<<<dim3(Dd / 128, (Bb * Ls) / 128), 256>>>(
        yg_p, out_proj_w, out, Bb * Ls, Dd, Dd);
}

// round 11
// speedup vs baseline: 1.2582x; 1.0963x over previous
#include <cuda_runtime.h>
#include <cuda_bf16.h>
#include <math.h>

// ---------------- problem constants ----------------
#define Bb   2
#define Ls   2048
#define Dd   1024
#define Kh   32
#define Hh   32
#define Mm   4
#define Aa   4
#define TOT  2080     // 2*D + K
#define CKc  4
#define HM   128      // H*M
#define CH   64       // scan chunk length (halved for 2 CTA/SM occupancy)
#define NC   32       // Ls / CH

// ---------------- scratch ----------------
__device__ float g_z[(size_t)Bb * Ls * TOT];
__device__ float g_xval[(size_t)Bb * Ls * Dd];
__device__ float g_gate[(size_t)Bb * Ls * Dd];
__device__ float g_pw[(size_t)Bb * Ls * Kh];
__device__ float g_yg[(size_t)Bb * Ls * Dd];
__device__ float g_csum_re[(size_t)Bb * Kh * NC * HM];
__device__ float g_csum_im[(size_t)Bb * Kh * NC * HM];
__device__ float g_cden[(size_t)Bb * Kh * NC];
__device__ float g_WnRe[HM * Hh];
__device__ float g_WnIm[HM * Hh];
__device__ float g_w3[3];
__device__ float g_slope[Kh];

__device__ __forceinline__ unsigned f2tf(float f) {
    unsigned u;
    asm("cvt.rna.tf32.f32 %0, %1;" : "=r"(u) : "f"(f));
    return u;
}

// ---------------- prep ----------------
__global__ void prep_kernel(const float* __restrict__ dlog,
                            const float* __restrict__ ns,
                            const float* __restrict__ Wre,
                            const float* __restrict__ Wim,
                            const float* __restrict__ ds,
                            const float* __restrict__ as_)
{
    int t = threadIdx.x;
    if (t == 0) {
        float mx = fmaxf(dlog[0], fmaxf(dlog[1], dlog[2]));
        float e0 = expf(dlog[0] - mx), e1 = expf(dlog[1] - mx), e2 = expf(dlog[2] - mx);
        float inv = 1.f / (e0 + e1 + e2);
        g_w3[0] = e0 * inv; g_w3[1] = e1 * inv; g_w3[2] = e2 * inv;
    }
    if (t < Kh) {
        float xx = (t < Kh - Aa) ? ds[t] : as_[t - (Kh - Aa)];
        g_slope[t] = (xx > 20.f) ? xx : log1pf(expf(xx));
    }
    for (int i = t; i < HM * Hh; i += blockDim.x) {
        int c = i / Hh;
        g_WnRe[i] = ns[c] * Wre[i];
        g_WnIm[i] = ns[HM + c] * Wim[i];
    }
}

// ---------------- 2-stage pipelined tf32 GEMM (R4 known-good, unchanged) ----
#define GPADK 20
#define GPADN 132

__global__ __launch_bounds__(256, 2)
void tf32_gemm_pipe(const float* __restrict__ A, const float* __restrict__ B,
                    float* __restrict__ C, int Mdim, int Ndim, int Kdim)
{
    __shared__ __align__(16) float As[2][128 * GPADK];
    __shared__ __align__(16) float Bs[2][16 * GPADN];

    const int n0 = blockIdx.x * 128;
    const int m0 = blockIdx.y * 128;
    const int tid  = threadIdx.x;
    const int wid  = tid >> 5;
    const int lane = tid & 31;
    const int g  = lane >> 2;
    const int t4 = lane & 3;
    const int wm = wid & 1;
    const int wn = wid >> 1;

    float acc[4][4][4];
#pragma unroll
    for (int i = 0; i < 4; i++)
#pragma unroll
        for (int j = 0; j < 4; j++)
#pragma unroll
            for (int r = 0; r < 4; r++) acc[i][j][r] = 0.f;

    auto stage = [&](int kt, int buf) {
        int k0 = kt * 16;
#pragma unroll
        for (int e = 0; e < 2; e++) {
            int f4 = tid * 2 + e;
            int row = f4 >> 2, c4 = f4 & 3;
            const float* src = A + (size_t)(m0 + row) * Kdim + k0 + c4 * 4;
            unsigned dst = (unsigned)__cvta_generic_to_shared(&As[buf][row * GPADK + c4 * 4]);
            asm volatile("cp.async.cg.shared.global [%0], [%1], 16;\n" :: "r"(dst), "l"(src));
        }
#pragma unroll
        for (int e = 0; e < 2; e++) {
            int f4 = tid * 2 + e;
            int kk = f4 >> 5, n4 = f4 & 31;
            int ncol = n0 + n4 * 4;
            float* dstp = &Bs[buf][kk * GPADN + n4 * 4];
            if (ncol + 3 < Ndim) {
                const float* src = B + (size_t)(k0 + kk) * Ndim + ncol;
                unsigned dst = (unsigned)__cvta_generic_to_shared(dstp);
                asm volatile("cp.async.cg.shared.global [%0], [%1], 16;\n" :: "r"(dst), "l"(src));
            } else {
#pragma unroll
                for (int j = 0; j < 4; j++)
                    dstp[j] = (ncol + j < Ndim) ? B[(size_t)(k0 + kk) * Ndim + ncol + j] : 0.f;
            }
        }
    };

    const int KT = Kdim / 16;
    stage(0, 0);
    asm volatile("cp.async.commit_group;\n" ::: "memory");

    for (int kt = 0; kt < KT; kt++) {
        int buf = kt & 1;
        if (kt + 1 < KT) {
            stage(kt + 1, buf ^ 1);
            asm volatile("cp.async.commit_group;\n" ::: "memory");
            asm volatile("cp.async.wait_group 1;\n" ::: "memory");
        } else {
            asm volatile("cp.async.wait_group 0;\n" ::: "memory");
        }
        __syncthreads();

        const float* Asb = As[buf];
        const float* Bsb = Bs[buf];
#pragma unroll
        for (int kk = 0; kk < 16; kk += 8) {
            unsigned af[4][4], bf[4][2];
#pragma unroll
            for (int mi = 0; mi < 4; mi++) {
                int mb = wm * 64 + mi * 16;
                const float* p0 = &Asb[(mb + g) * GPADK + kk + t4];
                const float* p1 = &Asb[(mb + 8 + g) * GPADK + kk + t4];
                af[mi][0] = f2tf(p0[0]); af[mi][1] = f2tf(p1[0]);
                af[mi][2] = f2tf(p0[4]); af[mi][3] = f2tf(p1[4]);
            }
#pragma unroll
            for (int ni = 0; ni < 4; ni++) {
                int nb = wn * 32 + ni * 8;
                bf[ni][0] = f2tf(Bsb[(kk + t4) * GPADN + nb + g]);
                bf[ni][1] = f2tf(Bsb[(kk + t4 + 4) * GPADN + nb + g]);
            }
#pragma unroll
            for (int mi = 0; mi < 4; mi++)
#pragma unroll
                for (int ni = 0; ni < 4; ni++) {
                    asm volatile(
                        "mma.sync.aligned.m16n8k8.row.col.f32.tf32.tf32.f32 "
                        "{%0,%1,%2,%3}, {%4,%5,%6,%7}, {%8,%9}, {%0,%1,%2,%3};\n"
                        : "+f"(acc[mi][ni][0]), "+f"(acc[mi][ni][1]),
                          "+f"(acc[mi][ni][2]), "+f"(acc[mi][ni][3])
                        : "r"(af[mi][0]), "r"(af[mi][1]),
                          "r"(af[mi][2]), "r"(af[mi][3]),
                          "r"(bf[ni][0]), "r"(bf[ni][1]));
                }
        }
        __syncthreads();
    }

#pragma unroll
    for (int mi = 0; mi < 4; mi++) {
        int r0 = m0 + wm * 64 + mi * 16 + g;
#pragma unroll
        for (int ni = 0; ni < 4; ni++) {
            int c0 = n0 + wn * 32 + ni * 8 + t4 * 2;
            if (c0 + 1 < Ndim) {
                C[(size_t)r0 * Ndim + c0]           = acc[mi][ni][0];
                C[(size_t)r0 * Ndim + c0 + 1]       = acc[mi][ni][1];
                C[(size_t)(r0 + 8) * Ndim + c0]     = acc[mi][ni][2];
                C[(size_t)(r0 + 8) * Ndim + c0 + 1] = acc[mi][ni][3];
            } else if (c0 < Ndim) {
                C[(size_t)r0 * Ndim + c0]       = acc[mi][ni][0];
                C[(size_t)(r0 + 8) * Ndim + c0] = acc[mi][ni][2];
            }
        }
    }
}

// ---------------- causal depthwise conv + split ----------------
__global__ void conv_kernel(const float* __restrict__ cw, const float* __restrict__ cb,
                            const float* __restrict__ sscale)
{
    int idx = blockIdx.x * blockDim.x + threadIdx.x;
    if (idx >= Bb * Ls * TOT) return;
    int c  = idx % TOT;
    int bl = idx / TOT;
    int l  = bl % Ls;

    float acc = cb[c];
#pragma unroll
    for (int j = 0; j < CKc; j++) {
        int ll = l - j;
        if (ll >= 0)
            acc += g_z[(size_t)(bl - j) * TOT + c] * cw[(CKc - 1 - j) * TOT + c];
    }
    if (c < Dd) {
        g_xval[(size_t)bl * Dd + c] = acc;
    } else if (c < 2 * Dd) {
        float sg = 1.f / (1.f + expf(-acc));
        g_gate[(size_t)bl * Dd + (c - Dd)] = acc * sg;
    } else {
        int k = c - 2 * Dd;
        float sr = sscale[k] * acc;
        sr = fminf(20.f, fmaxf(-20.f, sr));
        float p = expf(sr);
        float dist = (k < Kh - Aa) ? (float)(Ls - 1 - l) : (float)l;
        float tw = expf(-g_slope[k] * dist);
        g_pw[(size_t)bl * Kh + k] = p * tw;
    }
}

// ---------------- pass 1: per-(b,k,chunk) partial sums (smem-staged) --------
__global__ __launch_bounds__(128)
void csum_kernel(const float* __restrict__ theta)
{
    __shared__ float XV[CH * 33];
    __shared__ float PW[CH];

    int bi    = blockIdx.x;
    int chunk = bi % NC;
    int bk    = bi / NC;
    int k     = bk % Kh;
    int b     = bk / Kh;
    int c = threadIdx.x;
    int wid = c >> 5, lane = c & 31;
    int h = c >> 2, m = c & 3;

    size_t base = ((size_t)b * Ls + chunk * CH);
    const float* xvg = &g_xval[base * Dd + k * Hh];
    for (int r = wid; r < CH; r += 4)
        XV[r * 33 + lane] = xvg[(size_t)r * Dd + lane];
    if (c < CH)
        PW[c] = g_pw[(base + c) * Kh + k];
    __syncthreads();

    float th = theta[(k * Hh + h) * Mm + m];
    float w0 = g_w3[0], w1 = g_w3[1], w2 = g_w3[2];

    float are = 0.f, aim = 0.f, ad = 0.f;
    for (int i0 = 0; i0 < CH; i0 += 8) {
#pragma unroll
        for (int j = 0; j < 8; j++) {
            float xv = XV[(i0 + j) * 33 + h];
            float pwv = PW[i0 + j];
            float s, co; __sincosf(xv * th, &s, &co);
            float poly = w0 + xv * (w1 - w2 * xv);
            float t = pwv * poly;
            are += t * co; aim += t * s; ad += pwv;
        }
    }
    g_csum_re[(size_t)bi * HM + c] = are;
    g_csum_im[(size_t)bi * HM + c] = aim;
    if (c == 0) g_cden[bi] = ad;
}

// ---------------- pass 2: exclusive scan over chunks ----------------
__global__ __launch_bounds__(128)
void cscan_kernel()
{
    int bk = blockIdx.x;
    int c = threadIdx.x;
    float rr = 0.f, ri = 0.f;
    for (int ch = 0; ch < NC; ch++) {
        size_t idx = ((size_t)bk * NC + ch) * HM + c;
        float tr = g_csum_re[idx], ti = g_csum_im[idx];
        g_csum_re[idx] = rr; g_csum_im[idx] = ri;
        rr += tr; ri += ti;
    }
    if (c == 0) {
        float run = 0.f;
        for (int ch = 0; ch < NC; ch++) {
            float t = g_cden[bk * NC + ch];
            g_cden[bk * NC + ch] = run;
            run += t;
        }
    }
}

// ---------------- fused pass 3: scan + RMS scale + 3xTF32 head matvec -------
// One block per (bk, chunk of 64). 256 threads. 109 KB smem -> 2 CTAs/SM.
#define APAD  260                      // stride % 32 == 4 -> conflict-free frags
#define OFF_A    0                                  // 64 x 260
#define OFF_W    (OFF_A + CH * APAD)                // 16640
#define OFF_XV   (OFF_W + 32 * APAD)                // 24960
#define OFF_PW   (OFF_XV + CH * 33)                 // 27072
#define OFF_DEN  (OFF_PW + CH)                      // 27136
#define OFF_SC   (OFF_DEN + CH)                     // 27200
#define FUSED_FLOATS (OFF_SC + CH)                  // 27264
#define FUSED_SMEM_BYTES (FUSED_FLOATS * 4)         // 109056

__global__ __launch_bounds__(256)
void fused_scan_gemm(const float* __restrict__ theta)
{
    extern __shared__ float sm[];
    float* A   = sm + OFF_A;     // [pos 0..63][c 0..255]
    float* Ws  = sm + OFF_W;     // [hp 0..31][c 0..255]
    float* XV  = sm + OFF_XV;    // [pos][h]
    float* PW  = sm + OFF_PW;
    float* DEN = sm + OFF_DEN;
    float* SC  = sm + OFF_SC;

    const int bi    = blockIdx.x;
    const int chunk = bi % NC;
    const int bk    = bi / NC;
    const int k     = bk % Kh;
    const int b     = bk / Kh;
    const int tid  = threadIdx.x;
    const int wid  = tid >> 5;
    const int lane = tid & 31;
    const int base_l = chunk * CH;

    // ---- phase 1: cooperative staging ----
    const float* xvg = &g_xval[((size_t)b * Ls + base_l) * Dd + k * Hh];
    for (int r = wid; r < CH; r += 8)
        XV[r * 33 + lane] = xvg[(size_t)r * Dd + lane];
    if (tid < CH)
        PW[tid] = g_pw[((size_t)b * Ls + base_l + tid) * Kh + k];
    for (int idx = tid; idx < 256 * 32; idx += 256) {
        int cc = idx >> 5, hp = idx & 31;
        Ws[hp * APAD + cc] = (cc < HM) ? g_WnRe[cc * Hh + hp]
                                       : g_WnIm[(cc - HM) * Hh + hp];
    }
    __syncthreads();

    // ---- phase 2: warps 0-3 scan (A only); warp 4 den prefix (2 pos/lane) --
    if (tid < 128) {
        int c = tid;
        int h = c >> 2, m = c & 3;
        float th = theta[(k * Hh + h) * Mm + m];
        float w0 = g_w3[0], w1 = g_w3[1], w2 = g_w3[2];
        float are = g_csum_re[(size_t)bi * HM + c];
        float aim = g_csum_im[(size_t)bi * HM + c];

        for (int i0 = 0; i0 < CH; i0 += 8) {
#pragma unroll
            for (int j = 0; j < 8; j++) {
                int pos = i0 + j;
                float xv = XV[pos * 33 + h];
                float pwv = PW[pos];
                float s, co; __sincosf(xv * th, &s, &co);
                float poly = w0 + xv * (w1 - w2 * xv);
                float t = pwv * poly;
                are += t * co; aim += t * s;
                A[pos * APAD + c]       = are;
                A[pos * APAD + 128 + c] = aim;
            }
        }
    } else if (wid == 4) {
        float den0 = g_cden[bi];
        float p0 = PW[2 * lane], p1 = PW[2 * lane + 1];
        float s = p0 + p1;
        float scn = s;
#pragma unroll
        for (int o = 1; o < 32; o <<= 1) {
            float t = __shfl_up_sync(0xffffffffu, scn, o);
            if (lane >= o) scn += t;
        }
        float base = den0 + scn - s;   // exclusive prefix
        DEN[2 * lane]     = base + p0;
        DEN[2 * lane + 1] = base + s;
    }
    __syncthreads();

    // ---- phase 2b: position-parallel sum-of-squares + scale (8 pos/warp) ---
    for (int pos = wid; pos < CH; pos += 8) {
        const float* Ap = &A[pos * APAD];
        float sq = 0.f;
#pragma unroll
        for (int j = 0; j < 8; j++) {
            float v = Ap[j * 32 + lane];
            sq += v * v;
        }
#pragma unroll
        for (int o = 16; o > 0; o >>= 1)
            sq += __shfl_xor_sync(0xffffffffu, sq, o);
        if (lane == 0) {
            float inv_den = 1.f / fmaxf(DEN[pos], 1e-4f);
            float msq = inv_den * inv_den * sq * (1.f / (2.f * HM)) + 1e-5f;
            SC[pos] = inv_den * rsqrtf(msq);
        }
    }
    __syncthreads();

    // ---- phase 3: 8-warp 3xTF32 matvec (64 x 256) @ (256 x 32) -------------
    // warp = (m-tile wid>>1 of 4) x (N-half wid&1 of 2); 2 ni per warp.
    const int g  = lane >> 2;
    const int t4 = lane & 3;
    const int mt = wid >> 1;           // 0..3 -> 16 positions each
    const int nh = wid & 1;            // 0..1 -> 16 output cols each
    const int mb = mt * 16;

    float acc[2][4];
#pragma unroll
    for (int i = 0; i < 2; i++)
#pragma unroll
        for (int j = 0; j < 4; j++) acc[i][j] = 0.f;

    for (int kc = 0; kc < 256; kc += 8) {
        float ar[4];
        {
            const float* p0 = &A[(mb + g) * APAD + kc + t4];
            const float* p1 = &A[(mb + 8 + g) * APAD + kc + t4];
            ar[0] = p0[0]; ar[1] = p1[0]; ar[2] = p0[4]; ar[3] = p1[4];
        }
        unsigned ahi[4], alo[4];
#pragma unroll
        for (int i = 0; i < 4; i++) {
            ahi[i] = f2tf(ar[i]);
            alo[i] = f2tf(ar[i] - __uint_as_float(ahi[i]));
        }
#pragma unroll
        for (int ni = 0; ni < 2; ni++) {
            int nb = (nh * 2 + ni) * 8;
            float br0 = Ws[(nb + g) * APAD + kc + t4];
            float br1 = Ws[(nb + g) * APAD + kc + t4 + 4];
            unsigned bhi0 = f2tf(br0), bhi1 = f2tf(br1);
            unsigned blo0 = f2tf(br0 - __uint_as_float(bhi0));
            unsigned blo1 = f2tf(br1 - __uint_as_float(bhi1));
            asm volatile(
                "mma.sync.aligned.m16n8k8.row.col.f32.tf32.tf32.f32 "
                "{%0,%1,%2,%3}, {%4,%5,%6,%7}, {%8,%9}, {%0,%1,%2,%3};\n"
                : "+f"(acc[ni][0]), "+f"(acc[ni][1]), "+f"(acc[ni][2]), "+f"(acc[ni][3])
                : "r"(alo[0]), "r"(alo[1]), "r"(alo[2]), "r"(alo[3]),
                  "r"(bhi0), "r"(bhi1));
            asm volatile(
                "mma.sync.aligned.m16n8k8.row.col.f32.tf32.tf32.f32 "
                "{%0,%1,%2,%3}, {%4,%5,%6,%7}, {%8,%9}, {%0,%1,%2,%3};\n"
                : "+f"(acc[ni][0]), "+f"(acc[ni][1]), "+f"(acc[ni][2]), "+f"(acc[ni][3])
                : "r"(ahi[0]), "r"(ahi[1]), "r"(ahi[2]), "r"(ahi[3]),
                  "r"(blo0), "r"(blo1));
            asm volatile(
                "mma.sync.aligned.m16n8k8.row.col.f32.tf32.tf32.f32 "
                "{%0,%1,%2,%3}, {%4,%5,%6,%7}, {%8,%9}, {%0,%1,%2,%3};\n"
                : "+f"(acc[ni][0]), "+f"(acc[ni][1]), "+f"(acc[ni][2]), "+f"(acc[ni][3])
                : "r"(ahi[0]), "r"(ahi[1]), "r"(ahi[2]), "r"(ahi[3]),
                  "r"(bhi0), "r"(bhi1));
        }
    }

    // ---- epilogue: y = acc * scale * gate ----
    int p0 = mb + g;
    int p1 = p0 + 8;
    float sc0 = SC[p0], sc1 = SC[p1];
    size_t row0 = ((size_t)b * Ls + base_l + p0) * Dd + k * Hh;
    size_t row1 = ((size_t)b * Ls + base_l + p1) * Dd + k * Hh;
#pragma unroll
    for (int ni = 0; ni < 2; ni++) {
        int c0 = (nh * 2 + ni) * 8 + t4 * 2;
        g_yg[row0 + c0]     = acc[ni][0] * sc0 * g_gate[row0 + c0];
        g_yg[row0 + c0 + 1] = acc[ni][1] * sc0 * g_gate[row0 + c0 + 1];
        g_yg[row1 + c0]     = acc[ni][2] * sc1 * g_gate[row1 + c0];
        g_yg[row1 + c0 + 1] = acc[ni][3] * sc1 * g_gate[row1 + c0 + 1];
    }
}

// ---------------- launcher ----------------
extern "C" void kernel_launch(void* const* d_in, const int* in_sizes, int n_in,
                              void* d_out, int out_size)
{
    const float* x             = (const float*)d_in[0];
    const float* in_proj_w     = (const float*)d_in[1];
    const float* conv_w        = (const float*)d_in[2];
    const float* conv_b        = (const float*)d_in[3];
    const float* theta         = (const float*)d_in[4];
    const float* decay_slopes  = (const float*)d_in[5];
    const float* anchor_slopes = (const float*)d_in[6];
    const float* score_scale   = (const float*)d_in[7];
    const float* deriv_logits  = (const float*)d_in[8];
    const float* norm_scale    = (const float*)d_in[9];
    const float* W_re          = (const float*)d_in[10];
    const float* W_im          = (const float*)d_in[11];
    const float* out_proj_w    = (const float*)d_in[12];
    float* out = (float*)d_out;

    float *z_p = nullptr, *yg_p = nullptr;
    cudaGetSymbolAddress((void**)&z_p, g_z);
    cudaGetSymbolAddress((void**)&yg_p, g_yg);

    cudaFuncSetAttribute(fused_scan_gemm,
                         cudaFuncAttributeMaxDynamicSharedMemorySize,
                         FUSED_SMEM_BYTES);

    prep_kernel<<<1, 256>>>(deriv_logits, norm_scale, W_re, W_im,
                            decay_slopes, anchor_slopes);

    // z = x @ in_proj_w : (4096 x 1024) @ (1024 x 2080)
    tf32_gemm_pipe<<<dim3((TOT + 127) / 128, (Bb * Ls) / 128), 256>>>(
        x, in_proj_w, z_p, Bb * Ls, TOT, Dd);

    conv_kernel<<<(Bb * Ls * TOT + 255) / 256, 256>>>(conv_w, conv_b, score_scale);

    csum_kernel<<<Bb * Kh * NC, 128>>>(theta);
    cscan_kernel<<<Bb * Kh, 128>>>();
    fused_scan_gemm<<<Bb * Kh * NC, 256, FUSED_SMEM_BYTES>>>(theta);

    // out = yg @ out_proj_w : (4096 x 1024) @ (1024 x 1024)
    tf32_gemm_pipe<<<dim3(Dd / 128, (Bb * Ls) / 128), 256>>>(
        yg_p, out_proj_w, out, Bb * Ls, Dd, Dd);
}

// round 12
// speedup vs baseline: 1.3325x; 1.0590x over previous
#include <cuda_runtime.h>
#include <cuda_bf16.h>
#include <math.h>

// ---------------- problem constants ----------------
#define Bb   2
#define Ls   2048
#define Dd   1024
#define Kh   32
#define Hh   32
#define Mm   4
#define Aa   4
#define TOT  2080     // 2*D + K
#define CKc  4
#define HM   128      // H*M
#define CH   128      // scan chunk length
#define NC   16       // Ls / CH

// ---------------- scratch ----------------
__device__ float g_z[(size_t)Bb * Ls * TOT];
__device__ float g_xval[(size_t)Bb * Ls * Dd];
__device__ float g_gate[(size_t)Bb * Ls * Dd];
__device__ float g_pw[(size_t)Bb * Ls * Kh];
__device__ float g_yg[(size_t)Bb * Ls * Dd];
__device__ float g_num_re[(size_t)Bb * Kh * Ls * HM];   // 64 MB
__device__ float g_num_im[(size_t)Bb * Kh * Ls * HM];   // 64 MB
__device__ float g_scale[(size_t)Bb * Kh * Ls];
__device__ float g_csum_re[(size_t)Bb * Kh * NC * HM];
__device__ float g_csum_im[(size_t)Bb * Kh * NC * HM];
__device__ float g_cden[(size_t)Bb * Kh * NC];
__device__ float g_WnRe[HM * Hh];
__device__ float g_WnIm[HM * Hh];
__device__ float g_w3[3];
__device__ float g_slope[Kh];

__device__ __forceinline__ unsigned f2tf(float f) {
    unsigned u;
    asm("cvt.rna.tf32.f32 %0, %1;" : "=r"(u) : "f"(f));
    return u;
}

// ---------------- prep ----------------
__global__ void prep_kernel(const float* __restrict__ dlog,
                            const float* __restrict__ ns,
                            const float* __restrict__ Wre,
                            const float* __restrict__ Wim,
                            const float* __restrict__ ds,
                            const float* __restrict__ as_)
{
    int t = threadIdx.x;
    if (t == 0) {
        float mx = fmaxf(dlog[0], fmaxf(dlog[1], dlog[2]));
        float e0 = expf(dlog[0] - mx), e1 = expf(dlog[1] - mx), e2 = expf(dlog[2] - mx);
        float inv = 1.f / (e0 + e1 + e2);
        g_w3[0] = e0 * inv; g_w3[1] = e1 * inv; g_w3[2] = e2 * inv;
    }
    if (t < Kh) {
        float xx = (t < Kh - Aa) ? ds[t] : as_[t - (Kh - Aa)];
        g_slope[t] = (xx > 20.f) ? xx : log1pf(expf(xx));
    }
    for (int i = t; i < HM * Hh; i += blockDim.x) {
        int c = i / Hh;
        g_WnRe[i] = ns[c] * Wre[i];
        g_WnIm[i] = ns[HM + c] * Wim[i];
    }
}

// ---------------- 2-stage pipelined tf32 GEMM, BK=32, dynamic smem ----------
// C(MxN)=A(MxK)@B(KxN) row-major. BM=BN=128, BK=32.
#define GPADK 36
#define GPADN 132
#define AS_FLOATS (128 * GPADK)     // 4608
#define BS_FLOATS (32 * GPADN)      // 4224
#define GEMM_SMEM_BYTES ((2 * AS_FLOATS + 2 * BS_FLOATS) * 4)   // 70656

__global__ __launch_bounds__(256, 2)
void tf32_gemm_pipe(const float* __restrict__ A, const float* __restrict__ B,
                    float* __restrict__ C, int Mdim, int Ndim, int Kdim)
{
    extern __shared__ __align__(16) float gsm[];
    float* AsBase = gsm;
    float* BsBase = gsm + 2 * AS_FLOATS;

    const int n0 = blockIdx.x * 128;
    const int m0 = blockIdx.y * 128;
    const int tid  = threadIdx.x;
    const int wid  = tid >> 5;
    const int lane = tid & 31;
    const int g  = lane >> 2;
    const int t4 = lane & 3;
    const int wm = wid & 1;
    const int wn = wid >> 1;

    float acc[4][4][4];
#pragma unroll
    for (int i = 0; i < 4; i++)
#pragma unroll
        for (int j = 0; j < 4; j++)
#pragma unroll
            for (int r = 0; r < 4; r++) acc[i][j][r] = 0.f;

    auto stage = [&](int kt, int buf) {
        int k0 = kt * 32;
        float* Asb = AsBase + buf * AS_FLOATS;
        float* Bsb = BsBase + buf * BS_FLOATS;
        // A tile: 128 x 32 = 1024 float4, 4 per thread
#pragma unroll
        for (int e = 0; e < 4; e++) {
            int f4 = tid + e * 256;
            int row = f4 >> 3, c4 = f4 & 7;
            const float* src = A + (size_t)(m0 + row) * Kdim + k0 + c4 * 4;
            unsigned dst = (unsigned)__cvta_generic_to_shared(&Asb[row * GPADK + c4 * 4]);
            asm volatile("cp.async.cg.shared.global [%0], [%1], 16;\n" :: "r"(dst), "l"(src));
        }
        // B tile: 32 x 128 = 1024 float4, 4 per thread
#pragma unroll
        for (int e = 0; e < 4; e++) {
            int f4 = tid + e * 256;
            int kk = f4 >> 5, n4 = f4 & 31;
            int ncol = n0 + n4 * 4;
            float* dstp = &Bsb[kk * GPADN + n4 * 4];
            if (ncol + 3 < Ndim) {
                const float* src = B + (size_t)(k0 + kk) * Ndim + ncol;
                unsigned dst = (unsigned)__cvta_generic_to_shared(dstp);
                asm volatile("cp.async.cg.shared.global [%0], [%1], 16;\n" :: "r"(dst), "l"(src));
            } else {
#pragma unroll
                for (int j = 0; j < 4; j++)
                    dstp[j] = (ncol + j < Ndim) ? B[(size_t)(k0 + kk) * Ndim + ncol + j] : 0.f;
            }
        }
    };

    const int KT = Kdim / 32;
    stage(0, 0);
    asm volatile("cp.async.commit_group;\n" ::: "memory");

    for (int kt = 0; kt < KT; kt++) {
        int buf = kt & 1;
        if (kt + 1 < KT) {
            stage(kt + 1, buf ^ 1);
            asm volatile("cp.async.commit_group;\n" ::: "memory");
            asm volatile("cp.async.wait_group 1;\n" ::: "memory");
        } else {
            asm volatile("cp.async.wait_group 0;\n" ::: "memory");
        }
        __syncthreads();

        const float* Asb = AsBase + buf * AS_FLOATS;
        const float* Bsb = BsBase + buf * BS_FLOATS;
#pragma unroll
        for (int kk = 0; kk < 32; kk += 8) {
            unsigned af[4][4], bf[4][2];
#pragma unroll
            for (int mi = 0; mi < 4; mi++) {
                int mb = wm * 64 + mi * 16;
                const float* p0 = &Asb[(mb + g) * GPADK + kk + t4];
                const float* p1 = &Asb[(mb + 8 + g) * GPADK + kk + t4];
                af[mi][0] = f2tf(p0[0]); af[mi][1] = f2tf(p1[0]);
                af[mi][2] = f2tf(p0[4]); af[mi][3] = f2tf(p1[4]);
            }
#pragma unroll
            for (int ni = 0; ni < 4; ni++) {
                int nb = wn * 32 + ni * 8;
                bf[ni][0] = f2tf(Bsb[(kk + t4) * GPADN + nb + g]);
                bf[ni][1] = f2tf(Bsb[(kk + t4 + 4) * GPADN + nb + g]);
            }
#pragma unroll
            for (int mi = 0; mi < 4; mi++)
#pragma unroll
                for (int ni = 0; ni < 4; ni++) {
                    asm volatile(
                        "mma.sync.aligned.m16n8k8.row.col.f32.tf32.tf32.f32 "
                        "{%0,%1,%2,%3}, {%4,%5,%6,%7}, {%8,%9}, {%0,%1,%2,%3};\n"
                        : "+f"(acc[mi][ni][0]), "+f"(acc[mi][ni][1]),
                          "+f"(acc[mi][ni][2]), "+f"(acc[mi][ni][3])
                        : "r"(af[mi][0]), "r"(af[mi][1]),
                          "r"(af[mi][2]), "r"(af[mi][3]),
                          "r"(bf[ni][0]), "r"(bf[ni][1]));
                }
        }
        __syncthreads();
    }

#pragma unroll
    for (int mi = 0; mi < 4; mi++) {
        int r0 = m0 + wm * 64 + mi * 16 + g;
#pragma unroll
        for (int ni = 0; ni < 4; ni++) {
            int c0 = n0 + wn * 32 + ni * 8 + t4 * 2;
            if (c0 + 1 < Ndim) {
                C[(size_t)r0 * Ndim + c0]           = acc[mi][ni][0];
                C[(size_t)r0 * Ndim + c0 + 1]       = acc[mi][ni][1];
                C[(size_t)(r0 + 8) * Ndim + c0]     = acc[mi][ni][2];
                C[(size_t)(r0 + 8) * Ndim + c0 + 1] = acc[mi][ni][3];
            } else if (c0 < Ndim) {
                C[(size_t)r0 * Ndim + c0]       = acc[mi][ni][0];
                C[(size_t)(r0 + 8) * Ndim + c0] = acc[mi][ni][2];
            }
        }
    }
}

// ---------------- causal depthwise conv + split ----------------
__global__ void conv_kernel(const float* __restrict__ cw, const float* __restrict__ cb,
                            const float* __restrict__ sscale)
{
    int idx = blockIdx.x * blockDim.x + threadIdx.x;
    if (idx >= Bb * Ls * TOT) return;
    int c  = idx % TOT;
    int bl = idx / TOT;
    int l  = bl % Ls;

    float acc = cb[c];
#pragma unroll
    for (int j = 0; j < CKc; j++) {
        int ll = l - j;
        if (ll >= 0)
            acc += g_z[(size_t)(bl - j) * TOT + c] * cw[(CKc - 1 - j) * TOT + c];
    }
    if (c < Dd) {
        g_xval[(size_t)bl * Dd + c] = acc;
    } else if (c < 2 * Dd) {
        float sg = 1.f / (1.f + expf(-acc));
        g_gate[(size_t)bl * Dd + (c - Dd)] = acc * sg;
    } else {
        int k = c - 2 * Dd;
        float sr = sscale[k] * acc;
        sr = fminf(20.f, fmaxf(-20.f, sr));
        float p = expf(sr);
        float dist = (k < Kh - Aa) ? (float)(Ls - 1 - l) : (float)l;
        float tw = expf(-g_slope[k] * dist);
        g_pw[(size_t)bl * Kh + k] = p * tw;
    }
}

// ---------------- pass 1: per-(b,k,chunk) partial sums (smem-staged) --------
__global__ __launch_bounds__(128)
void csum_kernel(const float* __restrict__ theta)
{
    __shared__ float XV[CH * 33];
    __shared__ float PW[CH];

    int bi    = blockIdx.x;
    int chunk = bi % NC;
    int bk    = bi / NC;
    int k     = bk % Kh;
    int b     = bk / Kh;
    int c = threadIdx.x;
    int wid = c >> 5, lane = c & 31;
    int h = c >> 2, m = c & 3;

    size_t base = ((size_t)b * Ls + chunk * CH);
    const float* xvg = &g_xval[base * Dd + k * Hh];
    for (int r = wid; r < CH; r += 4)
        XV[r * 33 + lane] = xvg[(size_t)r * Dd + lane];
    PW[c] = g_pw[(base + c) * Kh + k];
    __syncthreads();

    float th = theta[(k * Hh + h) * Mm + m];
    float w0 = g_w3[0], w1 = g_w3[1], w2 = g_w3[2];

    float are = 0.f, aim = 0.f, ad = 0.f;
    for (int i0 = 0; i0 < CH; i0 += 8) {
#pragma unroll
        for (int j = 0; j < 8; j++) {
            float xv = XV[(i0 + j) * 33 + h];
            float pwv = PW[i0 + j];
            float s, co; __sincosf(xv * th, &s, &co);
            float poly = w0 + xv * (w1 - w2 * xv);
            float t = pwv * poly;
            are += t * co; aim += t * s; ad += pwv;
        }
    }
    g_csum_re[(size_t)bi * HM + c] = are;
    g_csum_im[(size_t)bi * HM + c] = aim;
    if (c == 0) g_cden[bi] = ad;
}

// ---------------- pass 2: exclusive scan over chunks ----------------
__global__ __launch_bounds__(128)
void cscan_kernel()
{
    int bk = blockIdx.x;
    int c = threadIdx.x;
    float rr = 0.f, ri = 0.f;
    for (int ch = 0; ch < NC; ch++) {
        size_t idx = ((size_t)bk * NC + ch) * HM + c;
        float tr = g_csum_re[idx], ti = g_csum_im[idx];
        g_csum_re[idx] = rr; g_csum_im[idx] = ri;
        rr += tr; ri += ti;
    }
    if (c == 0) {
        float run = 0.f;
        for (int ch = 0; ch < NC; ch++) {
            float t = g_cden[bk * NC + ch];
            g_cden[bk * NC + ch] = run;
            run += t;
        }
    }
}

// ---------------- pass 3: scan -> materialize num + per-position scale ------
__global__ __launch_bounds__(128)
void scan_kernel(const float* __restrict__ theta)
{
    __shared__ float sh_ws[32];   // [j(8)][warp(4)]

    int bi    = blockIdx.x;
    int chunk = bi % NC;
    int bk    = bi / NC;
    int k     = bk % Kh;
    int b     = bk / Kh;
    int c = threadIdx.x;
    int h = c >> 2, m = c & 3;
    int warp = c >> 5, lane = c & 31;

    float th = theta[(k * Hh + h) * Mm + m];
    float w0 = g_w3[0], w1 = g_w3[1], w2 = g_w3[2];
    float are = g_csum_re[(size_t)bi * HM + c];
    float aim = g_csum_im[(size_t)bi * HM + c];
    float den = g_cden[bi];

    int base_l = chunk * CH;
    size_t nbase = ((size_t)bk * Ls + base_l) * HM + c;
    const float* xvp = &g_xval[((size_t)b * Ls + base_l) * Dd + k * Hh + h];
    const float* pwp = &g_pw[((size_t)b * Ls + base_l) * Kh + k];

    for (int i0 = 0; i0 < CH; i0 += 8) {
        float xv8[8], pw8[8];
#pragma unroll
        for (int j = 0; j < 8; j++) {
            xv8[j] = xvp[(size_t)(i0 + j) * Dd];
            pw8[j] = pwp[(size_t)(i0 + j) * Kh];
        }
        float myden = 0.f;
#pragma unroll
        for (int j = 0; j < 8; j++) {
            float xv = xv8[j], pwv = pw8[j];
            float s, co; __sincosf(xv * th, &s, &co);
            float poly = w0 + xv * (w1 - w2 * xv);
            float t = pwv * poly;
            are += t * co; aim += t * s; den += pwv;
            g_num_re[nbase + (size_t)(i0 + j) * HM] = are;
            g_num_im[nbase + (size_t)(i0 + j) * HM] = aim;
            float sq = are * are + aim * aim;
#pragma unroll
            for (int o = 16; o > 0; o >>= 1) sq += __shfl_xor_sync(0xffffffffu, sq, o);
            if (lane == 0) sh_ws[j * 4 + warp] = sq;
            if (warp == 0 && lane == j) myden = den;
        }
        __syncthreads();
        if (warp == 0 && lane < 8) {
            float v = sh_ws[lane * 4] + sh_ws[lane * 4 + 1]
                    + sh_ws[lane * 4 + 2] + sh_ws[lane * 4 + 3];
            float inv_den = 1.f / fmaxf(myden, 1e-4f);
            float msq = inv_den * inv_den * v * (1.f / (2.f * HM)) + 1e-5f;
            g_scale[(size_t)bk * Ls + base_l + i0 + lane] = inv_den * rsqrtf(msq);
        }
        __syncthreads();
    }
}

// ---------------- head GEMM: y = scale * (num @ Wn) * gate, 3xTF32 ----------
#define HPADK 20
#define WPAD  260

__global__ __launch_bounds__(256)
void head_gemm_kernel()
{
    __shared__ __align__(16) float Ws[32 * WPAD];   // [hp][c 0..255]
    __shared__ __align__(16) float Ash[128 * HPADK];

    const int ltile = blockIdx.x;
    const int k     = blockIdx.y;
    const int tid  = threadIdx.x;
    const int wid  = tid >> 5;
    const int lane = tid & 31;
    const int g  = lane >> 2;
    const int t4 = lane & 3;
    const int r_base = ltile * 128;

    for (int idx = tid; idx < 256 * 32; idx += 256) {
        int cc = idx >> 5, hp = idx & 31;
        float v = (cc < HM) ? g_WnRe[cc * Hh + hp] : g_WnIm[(cc - HM) * Hh + hp];
        Ws[hp * WPAD + cc] = v;
    }

    float acc[4][4];
#pragma unroll
    for (int i = 0; i < 4; i++)
#pragma unroll
        for (int j = 0; j < 4; j++) acc[i][j] = 0.f;

    const int mb = wid * 16;

    for (int kc = 0; kc < 256; kc += 16) {
        __syncthreads();
#pragma unroll
        for (int e = 0; e < 2; e++) {
            int f4 = tid * 2 + e;
            int row = f4 >> 2, c4 = f4 & 3;
            int r = r_base + row;
            int b = r >> 11, l = r & (Ls - 1);
            int cc = kc + c4 * 4;
            const float* src = (cc < HM)
                ? &g_num_re[((size_t)(b * Kh + k) * Ls + l) * HM + cc]
                : &g_num_im[((size_t)(b * Kh + k) * Ls + l) * HM + (cc - HM)];
            float4 v = *reinterpret_cast<const float4*>(src);
            float* dst = &Ash[row * HPADK + c4 * 4];
            dst[0] = v.x; dst[1] = v.y; dst[2] = v.z; dst[3] = v.w;
        }
        __syncthreads();

#pragma unroll
        for (int kk = 0; kk < 16; kk += 8) {
            float ar[4];
            {
                const float* p0 = &Ash[(mb + g) * HPADK + kk + t4];
                const float* p1 = &Ash[(mb + 8 + g) * HPADK + kk + t4];
                ar[0] = p0[0]; ar[1] = p1[0]; ar[2] = p0[4]; ar[3] = p1[4];
            }
            unsigned ahi[4], alo[4];
#pragma unroll
            for (int i = 0; i < 4; i++) {
                ahi[i] = f2tf(ar[i]);
                alo[i] = f2tf(ar[i] - __uint_as_float(ahi[i]));
            }
#pragma unroll
            for (int ni = 0; ni < 4; ni++) {
                int nb = ni * 8;
                float br0 = Ws[(nb + g) * WPAD + kc + kk + t4];
                float br1 = Ws[(nb + g) * WPAD + kc + kk + t4 + 4];
                unsigned bhi0 = f2tf(br0), bhi1 = f2tf(br1);
                unsigned blo0 = f2tf(br0 - __uint_as_float(bhi0));
                unsigned blo1 = f2tf(br1 - __uint_as_float(bhi1));
                asm volatile(
                    "mma.sync.aligned.m16n8k8.row.col.f32.tf32.tf32.f32 "
                    "{%0,%1,%2,%3}, {%4,%5,%6,%7}, {%8,%9}, {%0,%1,%2,%3};\n"
                    : "+f"(acc[ni][0]), "+f"(acc[ni][1]), "+f"(acc[ni][2]), "+f"(acc[ni][3])
                    : "r"(alo[0]), "r"(alo[1]), "r"(alo[2]), "r"(alo[3]),
                      "r"(bhi0), "r"(bhi1));
                asm volatile(
                    "mma.sync.aligned.m16n8k8.row.col.f32.tf32.tf32.f32 "
                    "{%0,%1,%2,%3}, {%4,%5,%6,%7}, {%8,%9}, {%0,%1,%2,%3};\n"
                    : "+f"(acc[ni][0]), "+f"(acc[ni][1]), "+f"(acc[ni][2]), "+f"(acc[ni][3])
                    : "r"(ahi[0]), "r"(ahi[1]), "r"(ahi[2]), "r"(ahi[3]),
                      "r"(blo0), "r"(blo1));
                asm volatile(
                    "mma.sync.aligned.m16n8k8.row.col.f32.tf32.tf32.f32 "
                    "{%0,%1,%2,%3}, {%4,%5,%6,%7}, {%8,%9}, {%0,%1,%2,%3};\n"
                    : "+f"(acc[ni][0]), "+f"(acc[ni][1]), "+f"(acc[ni][2]), "+f"(acc[ni][3])
                    : "r"(ahi[0]), "r"(ahi[1]), "r"(ahi[2]), "r"(ahi[3]),
                      "r"(bhi0), "r"(bhi1));
            }
        }
    }

    int r0 = r_base + mb + g;
    int r1 = r0 + 8;
    int b0 = r0 >> 11, l0 = r0 & (Ls - 1);
    int b1 = r1 >> 11, l1 = r1 & (Ls - 1);
    float sc0 = g_scale[(size_t)(b0 * Kh + k) * Ls + l0];
    float sc1 = g_scale[(size_t)(b1 * Kh + k) * Ls + l1];
#pragma unroll
    for (int ni = 0; ni < 4; ni++) {
        int c0 = ni * 8 + t4 * 2;
        size_t i0 = (size_t)r0 * Dd + k * Hh + c0;
        size_t i1 = (size_t)r1 * Dd + k * Hh + c0;
        g_yg[i0]     = acc[ni][0] * sc0 * g_gate[i0];
        g_yg[i0 + 1] = acc[ni][1] * sc0 * g_gate[i0 + 1];
        g_yg[i1]     = acc[ni][2] * sc1 * g_gate[i1];
        g_yg[i1 + 1] = acc[ni][3] * sc1 * g_gate[i1 + 1];
    }
}

// ---------------- launcher ----------------
extern "C" void kernel_launch(void* const* d_in, const int* in_sizes, int n_in,
                              void* d_out, int out_size)
{
    const float* x             = (const float*)d_in[0];
    const float* in_proj_w     = (const float*)d_in[1];
    const float* conv_w        = (const float*)d_in[2];
    const float* conv_b        = (const float*)d_in[3];
    const float* theta         = (const float*)d_in[4];
    const float* decay_slopes  = (const float*)d_in[5];
    const float* anchor_slopes = (const float*)d_in[6];
    const float* score_scale   = (const float*)d_in[7];
    const float* deriv_logits  = (const float*)d_in[8];
    const float* norm_scale    = (const float*)d_in[9];
    const float* W_re          = (const float*)d_in[10];
    const float* W_im          = (const float*)d_in[11];
    const float* out_proj_w    = (const float*)d_in[12];
    float* out = (float*)d_out;

    float *z_p = nullptr, *yg_p = nullptr;
    cudaGetSymbolAddress((void**)&z_p, g_z);
    cudaGetSymbolAddress((void**)&yg_p, g_yg);

    cudaFuncSetAttribute(tf32_gemm_pipe,
                         cudaFuncAttributeMaxDynamicSharedMemorySize,
                         GEMM_SMEM_BYTES);

    prep_kernel<<<1, 256>>>(deriv_logits, norm_scale, W_re, W_im,
                            decay_slopes, anchor_slopes);

    // z = x @ in_proj_w : (4096 x 1024) @ (1024 x 2080)
    tf32_gemm_pipe<<<dim3((TOT + 127) / 128, (Bb * Ls) / 128), 256, GEMM_SMEM_BYTES>>>(
        x, in_proj_w, z_p, Bb * Ls, TOT, Dd);

    conv_kernel<<<(Bb * Ls * TOT + 255) / 256, 256>>>(conv_w, conv_b, score_scale);

    csum_kernel<<<Bb * Kh * NC, 128>>>(theta);
    cscan_kernel<<<Bb * Kh, 128>>>();
    scan_kernel<<<Bb * Kh * NC, 128>>>(theta);
    head_gemm_kernel<<<dim3((Bb * Ls) / 128, Kh), 256>>>();

    // out = yg @ out_proj_w : (4096 x 1024) @ (1024 x 1024)
    tf32_gemm_pipe<<<dim3(Dd / 128, (Bb * Ls) / 128), 256, GEMM_SMEM_BYTES>>>(
        yg_p, out_proj_w, out, Bb * Ls, Dd, Dd);
}

// round 13
// speedup vs baseline: 1.4152x; 1.0621x over previous
#include <cuda_runtime.h>
#include <cuda_bf16.h>
#include <math.h>

// ---------------- problem constants ----------------
#define Bb   2
#define Ls   2048
#define Dd   1024
#define Kh   32
#define Hh   32
#define Mm   4
#define Aa   4
#define TOT  2080     // 2*D + K
#define CKc  4
#define HM   128      // H*M
#define CH   128      // scan chunk length
#define NC   16       // Ls / CH

// ---------------- scratch ----------------
__device__ float g_z[(size_t)Bb * Ls * TOT];
__device__ float g_xval[(size_t)Bb * Ls * Dd];
__device__ float g_gate[(size_t)Bb * Ls * Dd];
__device__ float g_pw[(size_t)Bb * Ls * Kh];
__device__ float g_yg[(size_t)Bb * Ls * Dd];
__device__ float g_xr[(size_t)Bb * Ls * Dd];            // tf32-rounded x
__device__ float g_w1r[(size_t)Dd * TOT];               // tf32-rounded in_proj_w
__device__ float g_w2r[(size_t)Dd * Dd];                // tf32-rounded out_proj_w
__device__ float g_num_re[(size_t)Bb * Kh * Ls * HM];   // 64 MB
__device__ float g_num_im[(size_t)Bb * Kh * Ls * HM];   // 64 MB
__device__ float g_scale[(size_t)Bb * Kh * Ls];
__device__ float g_csum_re[(size_t)Bb * Kh * NC * HM];
__device__ float g_csum_im[(size_t)Bb * Kh * NC * HM];
__device__ float g_cden[(size_t)Bb * Kh * NC];
__device__ float g_WnRe[HM * Hh];
__device__ float g_WnIm[HM * Hh];
__device__ float g_w3[3];
__device__ float g_slope[Kh];

__device__ __forceinline__ unsigned f2tf(float f) {
    unsigned u;
    asm("cvt.rna.tf32.f32 %0, %1;" : "=r"(u) : "f"(f));
    return u;
}
__device__ __forceinline__ float tf32r(float f) {
    return __uint_as_float(f2tf(f));
}

// ---------------- prep ----------------
__global__ void prep_kernel(const float* __restrict__ dlog,
                            const float* __restrict__ ns,
                            const float* __restrict__ Wre,
                            const float* __restrict__ Wim,
                            const float* __restrict__ ds,
                            const float* __restrict__ as_)
{
    int t = threadIdx.x;
    if (t == 0) {
        float mx = fmaxf(dlog[0], fmaxf(dlog[1], dlog[2]));
        float e0 = expf(dlog[0] - mx), e1 = expf(dlog[1] - mx), e2 = expf(dlog[2] - mx);
        float inv = 1.f / (e0 + e1 + e2);
        g_w3[0] = e0 * inv; g_w3[1] = e1 * inv; g_w3[2] = e2 * inv;
    }
    if (t < Kh) {
        float xx = (t < Kh - Aa) ? ds[t] : as_[t - (Kh - Aa)];
        g_slope[t] = (xx > 20.f) ? xx : log1pf(expf(xx));
    }
    for (int i = t; i < HM * Hh; i += blockDim.x) {
        int c = i / Hh;
        g_WnRe[i] = ns[c] * Wre[i];
        g_WnIm[i] = ns[HM + c] * Wim[i];
    }
}

// ---------------- tf32 pre-rounding pass (float4) ----------------
__global__ void round_tf32_kernel(const float* __restrict__ src,
                                  float* __restrict__ dst, int n4)
{
    int i = blockIdx.x * blockDim.x + threadIdx.x;
    if (i < n4) {
        float4 v = reinterpret_cast<const float4*>(src)[i];
        v.x = tf32r(v.x); v.y = tf32r(v.y);
        v.z = tf32r(v.z); v.w = tf32r(v.w);
        reinterpret_cast<float4*>(dst)[i] = v;
    }
}

// ---------------- 2-stage pipelined tf32 GEMM, BK=32, pre-rounded inputs ----
// C(MxN)=A(MxK)@B(KxN) row-major. A and B MUST be tf32-pre-rounded.
#define GPADK 36
#define GPADN 132
#define AS_FLOATS (128 * GPADK)     // 4608
#define BS_FLOATS (32 * GPADN)      // 4224
#define GEMM_SMEM_BYTES ((2 * AS_FLOATS + 2 * BS_FLOATS) * 4)   // 70656

__global__ __launch_bounds__(256, 2)
void tf32_gemm_pipe(const float* __restrict__ A, const float* __restrict__ B,
                    float* __restrict__ C, int Mdim, int Ndim, int Kdim)
{
    extern __shared__ __align__(16) float gsm[];
    float* AsBase = gsm;
    float* BsBase = gsm + 2 * AS_FLOATS;

    const int n0 = blockIdx.x * 128;
    const int m0 = blockIdx.y * 128;
    const int tid  = threadIdx.x;
    const int wid  = tid >> 5;
    const int lane = tid & 31;
    const int g  = lane >> 2;
    const int t4 = lane & 3;
    const int wm = wid & 1;
    const int wn = wid >> 1;

    float acc[4][4][4];
#pragma unroll
    for (int i = 0; i < 4; i++)
#pragma unroll
        for (int j = 0; j < 4; j++)
#pragma unroll
            for (int r = 0; r < 4; r++) acc[i][j][r] = 0.f;

    auto stage = [&](int kt, int buf) {
        int k0 = kt * 32;
        float* Asb = AsBase + buf * AS_FLOATS;
        float* Bsb = BsBase + buf * BS_FLOATS;
#pragma unroll
        for (int e = 0; e < 4; e++) {
            int f4 = tid + e * 256;
            int row = f4 >> 3, c4 = f4 & 7;
            const float* src = A + (size_t)(m0 + row) * Kdim + k0 + c4 * 4;
            unsigned dst = (unsigned)__cvta_generic_to_shared(&Asb[row * GPADK + c4 * 4]);
            asm volatile("cp.async.cg.shared.global [%0], [%1], 16;\n" :: "r"(dst), "l"(src));
        }
#pragma unroll
        for (int e = 0; e < 4; e++) {
            int f4 = tid + e * 256;
            int kk = f4 >> 5, n4 = f4 & 31;
            int ncol = n0 + n4 * 4;
            float* dstp = &Bsb[kk * GPADN + n4 * 4];
            if (ncol + 3 < Ndim) {
                const float* src = B + (size_t)(k0 + kk) * Ndim + ncol;
                unsigned dst = (unsigned)__cvta_generic_to_shared(dstp);
                asm volatile("cp.async.cg.shared.global [%0], [%1], 16;\n" :: "r"(dst), "l"(src));
            } else {
#pragma unroll
                for (int j = 0; j < 4; j++)
                    dstp[j] = (ncol + j < Ndim) ? B[(size_t)(k0 + kk) * Ndim + ncol + j] : 0.f;
            }
        }
    };

    const int KT = Kdim / 32;
    stage(0, 0);
    asm volatile("cp.async.commit_group;\n" ::: "memory");

    for (int kt = 0; kt < KT; kt++) {
        int buf = kt & 1;
        if (kt + 1 < KT) {
            stage(kt + 1, buf ^ 1);
            asm volatile("cp.async.commit_group;\n" ::: "memory");
            asm volatile("cp.async.wait_group 1;\n" ::: "memory");
        } else {
            asm volatile("cp.async.wait_group 0;\n" ::: "memory");
        }
        __syncthreads();

        const float* Asb = AsBase + buf * AS_FLOATS;
        const float* Bsb = BsBase + buf * BS_FLOATS;
#pragma unroll
        for (int kk = 0; kk < 32; kk += 8) {
            unsigned af[4][4], bf[4][2];
#pragma unroll
            for (int mi = 0; mi < 4; mi++) {
                int mb = wm * 64 + mi * 16;
                const float* p0 = &Asb[(mb + g) * GPADK + kk + t4];
                const float* p1 = &Asb[(mb + 8 + g) * GPADK + kk + t4];
                af[mi][0] = __float_as_uint(p0[0]); af[mi][1] = __float_as_uint(p1[0]);
                af[mi][2] = __float_as_uint(p0[4]); af[mi][3] = __float_as_uint(p1[4]);
            }
#pragma unroll
            for (int ni = 0; ni < 4; ni++) {
                int nb = wn * 32 + ni * 8;
                bf[ni][0] = __float_as_uint(Bsb[(kk + t4) * GPADN + nb + g]);
                bf[ni][1] = __float_as_uint(Bsb[(kk + t4 + 4) * GPADN + nb + g]);
            }
#pragma unroll
            for (int mi = 0; mi < 4; mi++)
#pragma unroll
                for (int ni = 0; ni < 4; ni++) {
                    asm volatile(
                        "mma.sync.aligned.m16n8k8.row.col.f32.tf32.tf32.f32 "
                        "{%0,%1,%2,%3}, {%4,%5,%6,%7}, {%8,%9}, {%0,%1,%2,%3};\n"
                        : "+f"(acc[mi][ni][0]), "+f"(acc[mi][ni][1]),
                          "+f"(acc[mi][ni][2]), "+f"(acc[mi][ni][3])
                        : "r"(af[mi][0]), "r"(af[mi][1]),
                          "r"(af[mi][2]), "r"(af[mi][3]),
                          "r"(bf[ni][0]), "r"(bf[ni][1]));
                }
        }
        __syncthreads();
    }

#pragma unroll
    for (int mi = 0; mi < 4; mi++) {
        int r0 = m0 + wm * 64 + mi * 16 + g;
#pragma unroll
        for (int ni = 0; ni < 4; ni++) {
            int c0 = n0 + wn * 32 + ni * 8 + t4 * 2;
            if (c0 + 1 < Ndim) {
                C[(size_t)r0 * Ndim + c0]           = acc[mi][ni][0];
                C[(size_t)r0 * Ndim + c0 + 1]       = acc[mi][ni][1];
                C[(size_t)(r0 + 8) * Ndim + c0]     = acc[mi][ni][2];
                C[(size_t)(r0 + 8) * Ndim + c0 + 1] = acc[mi][ni][3];
            } else if (c0 < Ndim) {
                C[(size_t)r0 * Ndim + c0]       = acc[mi][ni][0];
                C[(size_t)(r0 + 8) * Ndim + c0] = acc[mi][ni][2];
            }
        }
    }
}

// ---------------- causal depthwise conv + split (float4) ----------------
__global__ void conv_kernel(const float* __restrict__ cw, const float* __restrict__ cb,
                            const float* __restrict__ sscale)
{
    int idx = blockIdx.x * blockDim.x + threadIdx.x;     // float4 index
    if (idx >= Bb * Ls * (TOT / 4)) return;
    int c4 = idx % (TOT / 4);
    int bl = idx / (TOT / 4);
    int l  = bl % Ls;
    int c  = c4 * 4;

    float4 acc = reinterpret_cast<const float4*>(cb)[c4];
#pragma unroll
    for (int j = 0; j < CKc; j++) {
        if (l - j >= 0) {
            float4 zv = *reinterpret_cast<const float4*>(&g_z[(size_t)(bl - j) * TOT + c]);
            float4 wv = *reinterpret_cast<const float4*>(&cw[(CKc - 1 - j) * TOT + c]);
            acc.x += zv.x * wv.x; acc.y += zv.y * wv.y;
            acc.z += zv.z * wv.z; acc.w += zv.w * wv.w;
        }
    }
    if (c < Dd) {
        *reinterpret_cast<float4*>(&g_xval[(size_t)bl * Dd + c]) = acc;
    } else if (c < 2 * Dd) {
        float4 o;
        o.x = acc.x / (1.f + expf(-acc.x));
        o.y = acc.y / (1.f + expf(-acc.y));
        o.z = acc.z / (1.f + expf(-acc.z));
        o.w = acc.w / (1.f + expf(-acc.w));
        *reinterpret_cast<float4*>(&g_gate[(size_t)bl * Dd + (c - Dd)]) = o;
    } else {
        int kbase = c - 2 * Dd;
        float a4[4] = {acc.x, acc.y, acc.z, acc.w};
#pragma unroll
        for (int j = 0; j < 4; j++) {
            int k = kbase + j;
            float sr = sscale[k] * a4[j];
            sr = fminf(20.f, fmaxf(-20.f, sr));
            float p = expf(sr);
            float dist = (k < Kh - Aa) ? (float)(Ls - 1 - l) : (float)l;
            float tw = expf(-g_slope[k] * dist);
            g_pw[(size_t)bl * Kh + k] = p * tw;
        }
    }
}

// ---------------- pass 1: per-(b,k,chunk) partial sums (smem-staged) --------
__global__ __launch_bounds__(128)
void csum_kernel(const float* __restrict__ theta)
{
    __shared__ float XV[CH * 33];
    __shared__ float PW[CH];

    int bi    = blockIdx.x;
    int chunk = bi % NC;
    int bk    = bi / NC;
    int k     = bk % Kh;
    int b     = bk / Kh;
    int c = threadIdx.x;
    int wid = c >> 5, lane = c & 31;
    int h = c >> 2, m = c & 3;

    size_t base = ((size_t)b * Ls + chunk * CH);
    const float* xvg = &g_xval[base * Dd + k * Hh];
    for (int r = wid; r < CH; r += 4)
        XV[r * 33 + lane] = xvg[(size_t)r * Dd + lane];
    PW[c] = g_pw[(base + c) * Kh + k];
    __syncthreads();

    float th = theta[(k * Hh + h) * Mm + m];
    float w0 = g_w3[0], w1 = g_w3[1], w2 = g_w3[2];

    float are = 0.f, aim = 0.f, ad = 0.f;
    for (int i0 = 0; i0 < CH; i0 += 8) {
#pragma unroll
        for (int j = 0; j < 8; j++) {
            float xv = XV[(i0 + j) * 33 + h];
            float pwv = PW[i0 + j];
            float s, co; __sincosf(xv * th, &s, &co);
            float poly = w0 + xv * (w1 - w2 * xv);
            float t = pwv * poly;
            are += t * co; aim += t * s; ad += pwv;
        }
    }
    g_csum_re[(size_t)bi * HM + c] = are;
    g_csum_im[(size_t)bi * HM + c] = aim;
    if (c == 0) g_cden[bi] = ad;
}

// ---------------- pass 2: exclusive scan over chunks ----------------
__global__ __launch_bounds__(128)
void cscan_kernel()
{
    int bk = blockIdx.x;
    int c = threadIdx.x;
    float rr = 0.f, ri = 0.f;
    for (int ch = 0; ch < NC; ch++) {
        size_t idx = ((size_t)bk * NC + ch) * HM + c;
        float tr = g_csum_re[idx], ti = g_csum_im[idx];
        g_csum_re[idx] = rr; g_csum_im[idx] = ri;
        rr += tr; ri += ti;
    }
    if (c == 0) {
        float run = 0.f;
        for (int ch = 0; ch < NC; ch++) {
            float t = g_cden[bk * NC + ch];
            g_cden[bk * NC + ch] = run;
            run += t;
        }
    }
}

// ---------------- pass 3: scan -> materialize num + per-position scale ------
__global__ __launch_bounds__(128)
void scan_kernel(const float* __restrict__ theta)
{
    __shared__ float sh_ws[32];   // [j(8)][warp(4)]

    int bi    = blockIdx.x;
    int chunk = bi % NC;
    int bk    = bi / NC;
    int k     = bk % Kh;
    int b     = bk / Kh;
    int c = threadIdx.x;
    int h = c >> 2, m = c & 3;
    int warp = c >> 5, lane = c & 31;

    float th = theta[(k * Hh + h) * Mm + m];
    float w0 = g_w3[0], w1 = g_w3[1], w2 = g_w3[2];
    float are = g_csum_re[(size_t)bi * HM + c];
    float aim = g_csum_im[(size_t)bi * HM + c];
    float den = g_cden[bi];

    int base_l = chunk * CH;
    size_t nbase = ((size_t)bk * Ls + base_l) * HM + c;
    const float* xvp = &g_xval[((size_t)b * Ls + base_l) * Dd + k * Hh + h];
    const float* pwp = &g_pw[((size_t)b * Ls + base_l) * Kh + k];

    for (int i0 = 0; i0 < CH; i0 += 8) {
        float xv8[8], pw8[8];
#pragma unroll
        for (int j = 0; j < 8; j++) {
            xv8[j] = xvp[(size_t)(i0 + j) * Dd];
            pw8[j] = pwp[(size_t)(i0 + j) * Kh];
        }
        float myden = 0.f;
#pragma unroll
        for (int j = 0; j < 8; j++) {
            float xv = xv8[j], pwv = pw8[j];
            float s, co; __sincosf(xv * th, &s, &co);
            float poly = w0 + xv * (w1 - w2 * xv);
            float t = pwv * poly;
            are += t * co; aim += t * s; den += pwv;
            g_num_re[nbase + (size_t)(i0 + j) * HM] = are;
            g_num_im[nbase + (size_t)(i0 + j) * HM] = aim;
            float sq = are * are + aim * aim;
#pragma unroll
            for (int o = 16; o > 0; o >>= 1) sq += __shfl_xor_sync(0xffffffffu, sq, o);
            if (lane == 0) sh_ws[j * 4 + warp] = sq;
            if (warp == 0 && lane == j) myden = den;
        }
        __syncthreads();
        if (warp == 0 && lane < 8) {
            float v = sh_ws[lane * 4] + sh_ws[lane * 4 + 1]
                    + sh_ws[lane * 4 + 2] + sh_ws[lane * 4 + 3];
            float inv_den = 1.f / fmaxf(myden, 1e-4f);
            float msq = inv_den * inv_den * v * (1.f / (2.f * HM)) + 1e-5f;
            g_scale[(size_t)bk * Ls + base_l + i0 + lane] = inv_den * rsqrtf(msq);
        }
        __syncthreads();
    }
}

// ---------------- head GEMM: y = scale * (num @ Wn) * gate, 3xTF32 ----------
#define HPADK 20
#define WPAD  260

__global__ __launch_bounds__(256)
void head_gemm_kernel()
{
    __shared__ __align__(16) float Ws[32 * WPAD];   // [hp][c 0..255]
    __shared__ __align__(16) float Ash[128 * HPADK];

    const int ltile = blockIdx.x;
    const int k     = blockIdx.y;
    const int tid  = threadIdx.x;
    const int wid  = tid >> 5;
    const int lane = tid & 31;
    const int g  = lane >> 2;
    const int t4 = lane & 3;
    const int r_base = ltile * 128;

    for (int idx = tid; idx < 256 * 32; idx += 256) {
        int cc = idx >> 5, hp = idx & 31;
        float v = (cc < HM) ? g_WnRe[cc * Hh + hp] : g_WnIm[(cc - HM) * Hh + hp];
        Ws[hp * WPAD + cc] = v;
    }

    float acc[4][4];
#pragma unroll
    for (int i = 0; i < 4; i++)
#pragma unroll
        for (int j = 0; j < 4; j++) acc[i][j] = 0.f;

    const int mb = wid * 16;

    for (int kc = 0; kc < 256; kc += 16) {
        __syncthreads();
#pragma unroll
        for (int e = 0; e < 2; e++) {
            int f4 = tid * 2 + e;
            int row = f4 >> 2, c4 = f4 & 3;
            int r = r_base + row;
            int b = r >> 11, l = r & (Ls - 1);
            int cc = kc + c4 * 4;
            const float* src = (cc < HM)
                ? &g_num_re[((size_t)(b * Kh + k) * Ls + l) * HM + cc]
                : &g_num_im[((size_t)(b * Kh + k) * Ls + l) * HM + (cc - HM)];
            float4 v = *reinterpret_cast<const float4*>(src);
            float* dst = &Ash[row * HPADK + c4 * 4];
            dst[0] = v.x; dst[1] = v.y; dst[2] = v.z; dst[3] = v.w;
        }
        __syncthreads();

#pragma unroll
        for (int kk = 0; kk < 16; kk += 8) {
            float ar[4];
            {
                const float* p0 = &Ash[(mb + g) * HPADK + kk + t4];
                const float* p1 = &Ash[(mb + 8 + g) * HPADK + kk + t4];
                ar[0] = p0[0]; ar[1] = p1[0]; ar[2] = p0[4]; ar[3] = p1[4];
            }
            unsigned ahi[4], alo[4];
#pragma unroll
            for (int i = 0; i < 4; i++) {
                ahi[i] = f2tf(ar[i]);
                alo[i] = f2tf(ar[i] - __uint_as_float(ahi[i]));
            }
#pragma unroll
            for (int ni = 0; ni < 4; ni++) {
                int nb = ni * 8;
                float br0 = Ws[(nb + g) * WPAD + kc + kk + t4];
                float br1 = Ws[(nb + g) * WPAD + kc + kk + t4 + 4];
                unsigned bhi0 = f2tf(br0), bhi1 = f2tf(br1);
                unsigned blo0 = f2tf(br0 - __uint_as_float(bhi0));
                unsigned blo1 = f2tf(br1 - __uint_as_float(bhi1));
                asm volatile(
                    "mma.sync.aligned.m16n8k8.row.col.f32.tf32.tf32.f32 "
                    "{%0,%1,%2,%3}, {%4,%5,%6,%7}, {%8,%9}, {%0,%1,%2,%3};\n"
                    : "+f"(acc[ni][0]), "+f"(acc[ni][1]), "+f"(acc[ni][2]), "+f"(acc[ni][3])
                    : "r"(alo[0]), "r"(alo[1]), "r"(alo[2]), "r"(alo[3]),
                      "r"(bhi0), "r"(bhi1));
                asm volatile(
                    "mma.sync.aligned.m16n8k8.row.col.f32.tf32.tf32.f32 "
                    "{%0,%1,%2,%3}, {%4,%5,%6,%7}, {%8,%9}, {%0,%1,%2,%3};\n"
                    : "+f"(acc[ni][0]), "+f"(acc[ni][1]), "+f"(acc[ni][2]), "+f"(acc[ni][3])
                    : "r"(ahi[0]), "r"(ahi[1]), "r"(ahi[2]), "r"(ahi[3]),
                      "r"(blo0), "r"(blo1));
                asm volatile(
                    "mma.sync.aligned.m16n8k8.row.col.f32.tf32.tf32.f32 "
                    "{%0,%1,%2,%3}, {%4,%5,%6,%7}, {%8,%9}, {%0,%1,%2,%3};\n"
                    : "+f"(acc[ni][0]), "+f"(acc[ni][1]), "+f"(acc[ni][2]), "+f"(acc[ni][3])
                    : "r"(ahi[0]), "r"(ahi[1]), "r"(ahi[2]), "r"(ahi[3]),
                      "r"(bhi0), "r"(bhi1));
            }
        }
    }

    int r0 = r_base + mb + g;
    int r1 = r0 + 8;
    int b0 = r0 >> 11, l0 = r0 & (Ls - 1);
    int b1 = r1 >> 11, l1 = r1 & (Ls - 1);
    float sc0 = g_scale[(size_t)(b0 * Kh + k) * Ls + l0];
    float sc1 = g_scale[(size_t)(b1 * Kh + k) * Ls + l1];
    // store tf32-pre-rounded (GEMM2 consumes raw bits; identical numerics to
    // the cvt-at-load it replaces)
#pragma unroll
    for (int ni = 0; ni < 4; ni++) {
        int c0 = ni * 8 + t4 * 2;
        size_t i0 = (size_t)r0 * Dd + k * Hh + c0;
        size_t i1 = (size_t)r1 * Dd + k * Hh + c0;
        g_yg[i0]     = tf32r(acc[ni][0] * sc0 * g_gate[i0]);
        g_yg[i0 + 1] = tf32r(acc[ni][1] * sc0 * g_gate[i0 + 1]);
        g_yg[i1]     = tf32r(acc[ni][2] * sc1 * g_gate[i1]);
        g_yg[i1 + 1] = tf32r(acc[ni][3] * sc1 * g_gate[i1 + 1]);
    }
}

// ---------------- launcher ----------------
extern "C" void kernel_launch(void* const* d_in, const int* in_sizes, int n_in,
                              void* d_out, int out_size)
{
    const float* x             = (const float*)d_in[0];
    const float* in_proj_w     = (const float*)d_in[1];
    const float* conv_w        = (const float*)d_in[2];
    const float* conv_b        = (const float*)d_in[3];
    const float* theta         = (const float*)d_in[4];
    const float* decay_slopes  = (const float*)d_in[5];
    const float* anchor_slopes = (const float*)d_in[6];
    const float* score_scale   = (const float*)d_in[7];
    const float* deriv_logits  = (const float*)d_in[8];
    const float* norm_scale    = (const float*)d_in[9];
    const float* W_re          = (const float*)d_in[10];
    const float* W_im          = (const float*)d_in[11];
    const float* out_proj_w    = (const float*)d_in[12];
    float* out = (float*)d_out;

    float *z_p = nullptr, *yg_p = nullptr, *xr_p = nullptr;
    float *w1r_p = nullptr, *w2r_p = nullptr;
    cudaGetSymbolAddress((void**)&z_p, g_z);
    cudaGetSymbolAddress((void**)&yg_p, g_yg);
    cudaGetSymbolAddress((void**)&xr_p, g_xr);
    cudaGetSymbolAddress((void**)&w1r_p, g_w1r);
    cudaGetSymbolAddress((void**)&w2r_p, g_w2r);

    cudaFuncSetAttribute(tf32_gemm_pipe,
                         cudaFuncAttributeMaxDynamicSharedMemorySize,
                         GEMM_SMEM_BYTES);

    prep_kernel<<<1, 256>>>(deriv_logits, norm_scale, W_re, W_im,
                            decay_slopes, anchor_slopes);

    // tf32 pre-round: x, in_proj_w, out_proj_w
    {
        int n4x = Bb * Ls * Dd / 4;
        round_tf32_kernel<<<(n4x + 255) / 256, 256>>>(x, xr_p, n4x);
        int n4w1 = Dd * TOT / 4;
        round_tf32_kernel<<<(n4w1 + 255) / 256, 256>>>(in_proj_w, w1r_p, n4w1);
        int n4w2 = Dd * Dd / 4;
        round_tf32_kernel<<<(n4w2 + 255) / 256, 256>>>(out_proj_w, w2r_p, n4w2);
    }

    // z = x @ in_proj_w : (4096 x 1024) @ (1024 x 2080)
    tf32_gemm_pipe<<<dim3((TOT + 127) / 128, (Bb * Ls) / 128), 256, GEMM_SMEM_BYTES>>>(
        xr_p, w1r_p, z_p, Bb * Ls, TOT, Dd);

    conv_kernel<<<(Bb * Ls * (TOT / 4) + 255) / 256, 256>>>(conv_w, conv_b, score_scale);

    csum_kernel<<<Bb * Kh * NC, 128>>>(theta);
    cscan_kernel<<<Bb * Kh, 128>>>();
    scan_kernel<<<Bb * Kh * NC, 128>>>(theta);
    head_gemm_kernel<<<dim3((Bb * Ls) / 128, Kh), 256>>>();

    // out = yg @ out_proj_w : (4096 x 1024) @ (1024 x 1024)
    tf32_gemm_pipe<<<dim3(Dd / 128, (Bb * Ls) / 128), 256, GEMM_SMEM_BYTES>>>(
        yg_p, w2r_p, out, Bb * Ls, Dd, Dd);
}